// round 13
// baseline (speedup 1.0000x reference)
#include <cuda_runtime.h>

// ---------------- problem constants ----------------
#define HW      4096
#define NPIX    (HW*HW)
#define NPATCH  64
#define K1      31458u   // loop1 continues iff count(v>th) <= 31457  <=>  v_(31458) <= th
#define K2      20972u   // loop2 continues iff count(v>th) >= 20972  <=>  v_(20972) >  th

// value window (verified per-patch; exact fallback if violated)
#define WLO     0x3F0E0000u   // ~0.5547
#define WHI     0x3F1A0000u   // ~0.6016
#define WSPAN   0xC0000u
#define NW1     768           // level-1 bins of 1024 keys each
#define W1SHIFT 10

#define RPB     16            // rows per blur block
#define BPPY    (512 / RPB)   // blur blocks per patch, vertically (32)
#define NBLK    (8 * (HW / RPB))   // total blur blocks (2048)

// ---------------- device scratch ----------------
__device__ float        g_blur[NPIX];
__device__ unsigned int g_bhist[NBLK][NW1];      // per-block hist (plain stores, no zeroing)
__device__ unsigned int g_babove[NBLK];
__device__ int          g_need [NPATCH];         // exact-fallback flag (plain store)
__device__ unsigned int g_sub  [NPATCH][2][1024];
__device__ unsigned int g_sel  [NPATCH][4];      // bin1, above1, bin2, above2
__device__ unsigned int g_key  [NPATCH][2];
__device__ float        g_th   [NPATCH];
__device__ unsigned int g_done = 0;              // last-block counter (reset after use)

// ---------------- K1: blur (circular register window, fully unrolled) + per-block hist ----
// Per-pixel 25-tap fmaf chain IDENTICAL to the passing version (kw outer, kh inner).
__device__ __forceinline__ void load_row(float* dst, const float* __restrict__ x,
                                         int yy, int c0, bool safe) {
    if (yy < 0 || yy >= HW) {
        #pragma unroll
        for (int j = 0; j < 12; j++) dst[j] = 0.0f;
    } else if (safe) {
        const float4* p = (const float4*)&x[yy * HW + c0 - 4];
        float4 a = __ldg(p), b = __ldg(p + 1), c = __ldg(p + 2);
        dst[0]=a.x; dst[1]=a.y; dst[2]=a.z;  dst[3]=a.w;
        dst[4]=b.x; dst[5]=b.y; dst[6]=b.z;  dst[7]=b.w;
        dst[8]=c.x; dst[9]=c.y; dst[10]=c.z; dst[11]=c.w;
    } else {
        #pragma unroll
        for (int j = 0; j < 12; j++) {
            int cc = c0 - 4 + j;
            dst[j] = (cc >= 0 && cc < HW) ? __ldg(&x[yy * HW + cc]) : 0.0f;
        }
    }
}

__global__ __launch_bounds__(128) void blur_hist(const float* __restrict__ x,
                                                 const float* __restrict__ bk) {
    __shared__ unsigned int wh[NW1];
    __shared__ unsigned int sred[4];
    for (int i = threadIdx.x; i < NW1; i += 128) wh[i] = 0u;
    __syncthreads();

    const float w  = bk[0];
    const int   c0 = blockIdx.x * 512 + threadIdx.x * 4;
    const int   y0 = blockIdx.y * RPB;
    const int   blk = blockIdx.y * 8 + blockIdx.x;
    const bool  safe = (c0 >= 4) && (c0 <= HW - 9);
    const int   lane = threadIdx.x & 31;
    unsigned int cntAbove = 0;

    float f[5][12];
    #pragma unroll
    for (int i = 0; i < 4; i++) load_row(f[i], x, y0 - 2 + i, c0, safe);

    #pragma unroll
    for (int k = 0; k < RPB; k++) {
        const int y = y0 + k;
        load_row(f[(k + 4) % 5], x, y + 2, c0, safe);

        float4 o;
        float* op = (float*)&o;
        #pragma unroll
        for (int u = 0; u < 4; u++) {
            float acc = 0.0f;
            #pragma unroll
            for (int j = 0; j < 5; j++)        // kw outer
                #pragma unroll
                for (int i = 0; i < 5; i++)    // kh inner (fastest) — Eigen order
                    acc = fmaf(f[(k + i) % 5][u + j + 2], w, acc);
            op[u] = acc;
            unsigned int key = __float_as_uint(acc);
            cntAbove += (key >= WHI) ? 1u : 0u;
            if (key - WLO < WSPAN)
                atomicAdd(&wh[(key - WLO) >> W1SHIFT], 1u);
        }
        *(float4*)&g_blur[y * HW + c0] = o;
    }

    #pragma unroll
    for (int off = 16; off; off >>= 1)
        cntAbove += __shfl_down_sync(0xffffffffu, cntAbove, off);
    if (lane == 0) sred[threadIdx.x >> 5] = cntAbove;
    __syncthreads();
    if (threadIdx.x == 0)
        g_babove[blk] = sred[0] + sred[1] + sred[2] + sred[3];
    for (int i = threadIdx.x; i < NW1; i += 128)
        g_bhist[blk][i] = wh[i];
}

// ---------------- warp inclusive suffix sum (lane..31) ----------------
__device__ __forceinline__ unsigned int warp_suffix(unsigned int v, int lane) {
    #pragma unroll
    for (int off = 1; off < 32; off <<= 1) {
        unsigned int u = __shfl_down_sync(0xffffffffu, v, off);
        if (lane + off < 32) v += u;
    }
    return v;
}

// ---------------- K2: sum block hists, locate level-1 bins (2-barrier scan) -------------
__global__ __launch_bounds__(1024) void coarse_select_win() {
    __shared__ unsigned int ws[32];
    __shared__ unsigned int sw[32];
    __shared__ unsigned int sga;
    const int p = blockIdx.x, t = threadIdx.x;
    const int lane = t & 31, wid = t >> 5;
    const int pr = p >> 3, pc = p & 7;

    // zero the sub-hist for this patch (runs before refine_pass)
    g_sub[p][0][t] = 0u;
    g_sub[p][1][t] = 0u;

    // sum the per-block hists (bins >= NW1 are zero)
    unsigned int c = 0;
    if (t < NW1) {
        #pragma unroll 4
        for (int s = 0; s < BPPY; s++)
            c += g_bhist[(pr * BPPY + s) * 8 + pc][t];
    }
    unsigned int s = warp_suffix(c, lane);
    if (lane == 0) ws[wid] = s;

    if (wid == 1) {  // warp 1 also sums the per-block above-counts (BPPY = 32)
        unsigned int a = g_babove[(pr * BPPY + lane) * 8 + pc];
        #pragma unroll
        for (int off = 16; off; off >>= 1)
            a += __shfl_down_sync(0xffffffffu, a, off);
        if (lane == 0) sga = a;
    }
    __syncthreads();
    if (wid == 0) sw[lane] = warp_suffix(ws[lane], lane);
    __syncthreads();

    const unsigned int ga = sga;
    const unsigned int total_in = sw[0];
    unsigned int above = (s - c) + ((wid < 31) ? sw[wid + 1] : 0u) + ga;

    if (t == 0)
        g_need[p] = (ga >= K2) || (ga + total_in < K1) ? 1 : 0;

    if (above < K1 && K1 <= above + c) { g_sel[p][0] = (unsigned)t; g_sel[p][1] = above; }
    if (above < K2 && K2 <= above + c) { g_sel[p][2] = (unsigned)t; g_sel[p][3] = above; }
}

// ---------------- K3a: sub-histogram, full re-read of g_blur (4x float4/iter) --------------
__global__ __launch_bounds__(256) void refine_pass() {
    __shared__ unsigned int sbin[NPATCH][2];
    if (threadIdx.x < NPATCH) {
        sbin[threadIdx.x][0] = g_sel[threadIdx.x][0];
        sbin[threadIdx.x][1] = g_sel[threadIdx.x][2];
    }
    __syncthreads();
    const float4* b4 = (const float4*)g_blur;
    const unsigned int stride = gridDim.x * 256;   // 524288; NPIX/4/stride = 8 exactly
    const unsigned int i0 = blockIdx.x * 256 + threadIdx.x;
    #pragma unroll
    for (int rep = 0; rep < 2; rep++) {
        unsigned int base = i0 + rep * 4 * stride;
        float4 v0 = __ldg(&b4[base]);
        float4 v1 = __ldg(&b4[base + stride]);
        float4 v2 = __ldg(&b4[base + 2 * stride]);
        float4 v3 = __ldg(&b4[base + 3 * stride]);
        #pragma unroll
        for (int h = 0; h < 4; h++) {
            unsigned int ii = base + h * stride;
            const float4& vv = h == 0 ? v0 : h == 1 ? v1 : h == 2 ? v2 : v3;
            const float* vp = (const float*)&vv;
            int y = ii >> 10;
            int p = ((y >> 9) << 3) + ((ii & 1023u) >> 7);
            #pragma unroll
            for (int u = 0; u < 4; u++) {
                unsigned int wk = __float_as_uint(vp[u]) - WLO;
                if (wk < WSPAN) {
                    unsigned int bin = wk >> W1SHIFT;
                    if (bin == sbin[p][0]) atomicAdd(&g_sub[p][0][wk & 1023u], 1u);
                    if (bin == sbin[p][1]) atomicAdd(&g_sub[p][1][wk & 1023u], 1u);
                }
            }
        }
    }
}

// ---------------- K4: walk (bit-faithful, unrolled dependent chain) ----------------
__device__ __forceinline__ float walk_down(float th, float A) {
    for (int g = 0; g < 20000; g++) {
        if (!(A <= th)) return th;
        float t1  = th  - 0.0005f; if (A > t1)  return t1;
        float t2  = t1  - 0.0005f; if (A > t2)  return t2;
        float t3  = t2  - 0.0005f; if (A > t3)  return t3;
        float t4  = t3  - 0.0005f; if (A > t4)  return t4;
        float t5  = t4  - 0.0005f; if (A > t5)  return t5;
        float t6  = t5  - 0.0005f; if (A > t6)  return t6;
        float t7  = t6  - 0.0005f; if (A > t7)  return t7;
        float t8  = t7  - 0.0005f; if (A > t8)  return t8;
        float t9  = t8  - 0.0005f; if (A > t9)  return t9;
        float t10 = t9  - 0.0005f; if (A > t10) return t10;
        float t11 = t10 - 0.0005f; if (A > t11) return t11;
        float t12 = t11 - 0.0005f; if (A > t12) return t12;
        float t13 = t12 - 0.0005f; if (A > t13) return t13;
        float t14 = t13 - 0.0005f; if (A > t14) return t14;
        float t15 = t14 - 0.0005f; if (A > t15) return t15;
        th = t15 - 0.0005f;
    }
    return th;
}
__device__ __forceinline__ float walk_up(float th, float B) {
    for (int g = 0; g < 20000; g++) {
        if (!(B > th)) return th;
        float t1  = th  + 0.0005f; if (B <= t1)  return t1;
        float t2  = t1  + 0.0005f; if (B <= t2)  return t2;
        float t3  = t2  + 0.0005f; if (B <= t3)  return t3;
        float t4  = t3  + 0.0005f; if (B <= t4)  return t4;
        float t5  = t4  + 0.0005f; if (B <= t5)  return t5;
        float t6  = t5  + 0.0005f; if (B <= t6)  return t6;
        float t7  = t6  + 0.0005f; if (B <= t7)  return t7;
        float t8  = t7  + 0.0005f; if (B <= t8)  return t8;
        float t9  = t8  + 0.0005f; if (B <= t9)  return t9;
        float t10 = t9  + 0.0005f; if (B <= t10) return t10;
        float t11 = t10 + 0.0005f; if (B <= t11) return t11;
        float t12 = t11 + 0.0005f; if (B <= t12) return t12;
        float t13 = t12 + 0.0005f; if (B <= t13) return t13;
        float t14 = t13 + 0.0005f; if (B <= t14) return t14;
        float t15 = t14 + 0.0005f; if (B <= t15) return t15;
        th = t15 + 0.0005f;
    }
    return th;
}

// ---------------- K3b: exact key within level-1 bin (+ fallback) + fused walk -------------
__global__ __launch_bounds__(1024) void refine_select_fb() {
    __shared__ unsigned int ws[32];
    __shared__ unsigned int sw[32];
    __shared__ unsigned int scnt;
    const int p = blockIdx.x, t = threadIdx.x;
    const int lane = t & 31, wid = t >> 5;

    if (!g_need[p]) {
        for (int q = 0; q < 2; q++) {
            const unsigned int bin = g_sel[p][q * 2];
            const unsigned int ab  = g_sel[p][q * 2 + 1];
            const unsigned int r   = (q ? K2 : K1) - ab;

            unsigned int c = g_sub[p][q][t];
            unsigned int s = warp_suffix(c, lane);
            if (lane == 0) ws[wid] = s;
            __syncthreads();
            if (wid == 0) sw[lane] = warp_suffix(ws[lane], lane);
            if (t == 0) g_key[p][q] = WLO + (bin << W1SHIFT);
            __syncthreads();
            unsigned int above = (s - c) + ((wid < 31) ? sw[wid + 1] : 0u);
            if (above < r && r <= above + c)
                g_key[p][q] = WLO + (bin << W1SHIFT) + (unsigned)t;
            __syncthreads();
        }
    } else {
        // exact fallback: binary search on the key over the whole patch
        const float* base = g_blur + ((p >> 3) * 512) * HW + (p & 7) * 512;
        for (int q = 0; q < 2; q++) {
            const unsigned int K = q ? K2 : K1;
            unsigned int lo = 0u, hi = 0x40000000u;
            while (hi - lo > 1u) {
                unsigned int mid = lo + ((hi - lo) >> 1);
                unsigned int cnt = 0;
                for (int i = t; i < 512 * 512; i += 1024) {
                    unsigned int key = __float_as_uint(base[(i >> 9) * HW + (i & 511)]);
                    cnt += (key >= mid) ? 1u : 0u;
                }
                #pragma unroll
                for (int off = 16; off; off >>= 1)
                    cnt += __shfl_down_sync(0xffffffffu, cnt, off);
                if (lane == 0) ws[wid] = cnt;
                __syncthreads();
                if (t == 0) {
                    unsigned int s = 0;
                    for (int i = 0; i < 32; i++) s += ws[i];
                    scnt = s;
                }
                __syncthreads();
                if (scnt >= K) lo = mid; else hi = mid;
                __syncthreads();
            }
            if (t == 0) g_key[p][q] = lo;
            __syncthreads();
        }
    }

    // ---- fused walk: last block to finish runs the serial threshold walk ----
    __syncthreads();
    __threadfence();
    if (t == 0) {
        unsigned int v = atomicAdd(&g_done, 1u);
        if (v == NPATCH - 1) {
            __threadfence();
            float th = 0.5f;
            for (int pp = 0; pp < NPATCH; pp++) {
                float A = __uint_as_float(*((volatile unsigned int*)&g_key[pp][0]));
                float B = __uint_as_float(*((volatile unsigned int*)&g_key[pp][1]));
                th = walk_down(th, A);
                th = walk_up(th, B);
                g_th[pp] = th;
            }
            __threadfence();
            g_done = 0;   // reset for graph replay determinism
        }
    }
}

// ---------------- K5: bit-packed binarize + close (dilate5, erode5) ----------------
#define CTW  256
#define CTH  128
#define WPR  10
#define TROWS 136
__global__ __launch_bounds__(256) void close_k(float* __restrict__ out) {
    __shared__ unsigned int A[TROWS][WPR];
    __shared__ unsigned int B[TROWS][WPR];
    __shared__ float sth[NPATCH];
    const int t = threadIdx.x;
    if (t < NPATCH) sth[t] = g_th[t];
    __syncthreads();

    const int gx0 = blockIdx.x * CTW;
    const int gy0 = blockIdx.y * CTH;
    const int lane = t & 31, wid = t >> 5;
    const bool xsafe = (gx0 >= 32) && (gx0 + CTW + 32 <= HW);

    // binarize -> packed words
    for (int rr = 0; rr < TROWS / 8; rr++) {       // 17 rows per warp
        const int r  = wid + rr * 8;
        const int gy = gy0 + r - 4;
        const bool gyok = (unsigned)gy < HW;
        if (xsafe && gyok) {
            // fast path: float4 loads + shfl-OR word assembly
            const float4* rowp = (const float4*)(g_blur + (size_t)gy * HW + (gx0 - 32));
            const int prow = (gy >> 9) << 3;
            // chunk A: px 0..127 -> words 0..3 ; chunk B: px 128..255 -> words 4..7
            #pragma unroll
            for (int ch = 0; ch < 2; ch++) {
                float4 a = rowp[ch * 32 + lane];
                int gx = gx0 - 32 + ch * 128 + lane * 4;
                float th = sth[prow + (gx >> 9)];
                unsigned int nib = (unsigned)(a.x > th) | ((unsigned)(a.y > th) << 1)
                                 | ((unsigned)(a.z > th) << 2) | ((unsigned)(a.w > th) << 3);
                unsigned int comb = nib << ((lane & 7) * 4);
                comb |= __shfl_xor_sync(0xffffffffu, comb, 1);
                comb |= __shfl_xor_sync(0xffffffffu, comb, 2);
                comb |= __shfl_xor_sync(0xffffffffu, comb, 4);
                if ((lane & 7) == 0) A[r][ch * 4 + (lane >> 3)] = comb;
            }
            // chunk C: px 256..319 -> words 8..9 (lanes 0..15)
            if (lane < 16) {
                float4 a = rowp[64 + lane];
                int gx = gx0 - 32 + 256 + lane * 4;
                float th = sth[prow + (gx >> 9)];
                unsigned int nib = (unsigned)(a.x > th) | ((unsigned)(a.y > th) << 1)
                                 | ((unsigned)(a.z > th) << 2) | ((unsigned)(a.w > th) << 3);
                unsigned int comb = nib << ((lane & 7) * 4);
                comb |= __shfl_xor_sync(0x0000ffffu, comb, 1);
                comb |= __shfl_xor_sync(0x0000ffffu, comb, 2);
                comb |= __shfl_xor_sync(0x0000ffffu, comb, 4);
                if ((lane & 7) == 0) A[r][8 + (lane >> 3)] = comb;
            }
        } else if (!gyok) {
            if (lane < WPR) A[r][lane] = 0u;
        } else {
            // guarded path (x-edge blocks): batched loads then ballots
            float v[WPR];
            #pragma unroll
            for (int wc = 0; wc < WPR; wc++) {
                int gx = gx0 + (wc - 1) * 32 + lane;
                v[wc] = ((unsigned)gx < HW) ? g_blur[(size_t)gy * HW + gx] : 0.0f;
            }
            #pragma unroll
            for (int wc = 0; wc < WPR; wc++) {
                int gx = gx0 + (wc - 1) * 32 + lane;
                unsigned int bit = 0;
                if ((unsigned)gx < HW)
                    bit = (v[wc] > sth[((gy >> 9) << 3) + (gx >> 9)]) ? 1u : 0u;
                unsigned int word = __ballot_sync(0xffffffffu, bit);
                if (lane == 0) A[r][wc] = word;
            }
        }
    }
    __syncthreads();

    for (int i = t; i < TROWS * WPR; i += 256) {
        int r = i / WPR, wc = i % WPR;
        unsigned int wv = A[r][wc];
        unsigned int lw = wc > 0       ? A[r][wc - 1] : 0u;
        unsigned int rw = wc < WPR - 1 ? A[r][wc + 1] : 0u;
        B[r][wc] = wv | __funnelshift_r(wv, rw, 1) | __funnelshift_r(wv, rw, 2)
                      | __funnelshift_l(lw, wv, 1) | __funnelshift_l(lw, wv, 2);
    }
    __syncthreads();

    for (int i = t; i < TROWS * WPR; i += 256) {
        int r = i / WPR, wc = i % WPR;
        unsigned int d = 0u;
        if (r >= 2 && r < TROWS - 2)
            d = B[r-2][wc] | B[r-1][wc] | B[r][wc] | B[r+1][wc] | B[r+2][wc];
        int gy = gy0 + r - 4;
        bool xout = (wc == 0 && gx0 == 0) || (wc == WPR - 1 && gx0 + CTW == HW);
        if ((unsigned)gy >= HW || xout) d = 0xffffffffu;
        A[r][wc] = d;
    }
    __syncthreads();

    for (int i = t; i < TROWS * WPR; i += 256) {
        int r = i / WPR, wc = i % WPR;
        unsigned int wv = A[r][wc];
        unsigned int lw = wc > 0       ? A[r][wc - 1] : 0xffffffffu;
        unsigned int rw = wc < WPR - 1 ? A[r][wc + 1] : 0xffffffffu;
        B[r][wc] = wv & __funnelshift_r(wv, rw, 1) & __funnelshift_r(wv, rw, 2)
                      & __funnelshift_l(lw, wv, 1) & __funnelshift_l(lw, wv, 2);
    }
    __syncthreads();

    for (int i = t; i < CTH * 8; i += 256) {
        int r = (i >> 3) + 4, wc = (i & 7) + 1;
        unsigned int v = B[r-2][wc] & B[r-1][wc] & B[r][wc] & B[r+1][wc] & B[r+2][wc];
        int gy = gy0 + r - 4;
        int gx = gx0 + (wc - 1) * 32;
        float4* o = (float4*)&out[(size_t)gy * HW + gx];
        #pragma unroll
        for (int q = 0; q < 8; q++) {
            float4 fv;
            fv.x = (v >> (q * 4 + 0)) & 1u ? 1.0f : 0.0f;
            fv.y = (v >> (q * 4 + 1)) & 1u ? 1.0f : 0.0f;
            fv.z = (v >> (q * 4 + 2)) & 1u ? 1.0f : 0.0f;
            fv.w = (v >> (q * 4 + 3)) & 1u ? 1.0f : 0.0f;
            o[q] = fv;
        }
    }
}

// ---------------- launch ----------------
extern "C" void kernel_launch(void* const* d_in, const int* in_sizes, int n_in,
                              void* d_out, int out_size) {
    const float* x  = (const float*)d_in[0];
    const float* bk = (const float*)d_in[1];
    float* out = (float*)d_out;
    (void)in_sizes; (void)n_in; (void)out_size;

    blur_hist<<<dim3(HW / 512, HW / RPB), 128>>>(x, bk);
    coarse_select_win<<<NPATCH, 1024>>>();
    refine_pass<<<2048, 256>>>();
    refine_select_fb<<<NPATCH, 1024>>>();   // walk fused (last block)
    close_k<<<dim3(HW / CTW, HW / CTH), 256>>>(out);
}

// round 14
// speedup vs baseline: 1.1857x; 1.1857x over previous
#include <cuda_runtime.h>

// ---------------- problem constants ----------------
#define HW      4096
#define NPIX    (HW*HW)
#define NPATCH  64
#define K1      31458u   // loop1 continues iff count(v>th) <= 31457  <=>  v_(31458) <= th
#define K2      20972u   // loop2 continues iff count(v>th) >= 20972  <=>  v_(20972) >  th

// value window (verified per-patch; exact fallback if violated)
#define WLO     0x3F0E0000u   // ~0.5547
#define WHI     0x3F1A0000u   // ~0.6016
#define WSPAN   0xC0000u
#define NW1     768           // level-1 bins of 1024 keys each
#define W1SHIFT 10

#define RPB     16            // rows per blur block
#define BPPY    (512 / RPB)   // blur blocks per patch, vertically (32)
#define NBLK    (8 * (HW / RPB))   // total blur blocks (2048)

// ---------------- device scratch ----------------
__device__ float        g_blur[NPIX];
__device__ unsigned int g_bhist[NBLK][NW1];      // per-block hist (plain stores, no zeroing)
__device__ unsigned int g_babove[NBLK];
__device__ int          g_need [NPATCH];         // exact-fallback flag (plain store)
__device__ unsigned int g_sub  [NPATCH][2][1024];
__device__ unsigned int g_sel  [NPATCH][4];      // bin1, above1, bin2, above2
__device__ unsigned int g_key  [NPATCH][2];
__device__ float        g_th   [NPATCH];
__device__ unsigned int g_done = 0;              // last-block counter (reset after use)

// ---------------- K1: blur (circular register window, fully unrolled) + per-block hist ----
// Per-pixel 25-tap fmaf chain IDENTICAL to the passing version (kw outer, kh inner).
__device__ __forceinline__ void load_row(float* dst, const float* __restrict__ x,
                                         int yy, int c0, bool safe) {
    if (yy < 0 || yy >= HW) {
        #pragma unroll
        for (int j = 0; j < 12; j++) dst[j] = 0.0f;
    } else if (safe) {
        const float4* p = (const float4*)&x[yy * HW + c0 - 4];
        float4 a = __ldg(p), b = __ldg(p + 1), c = __ldg(p + 2);
        dst[0]=a.x; dst[1]=a.y; dst[2]=a.z;  dst[3]=a.w;
        dst[4]=b.x; dst[5]=b.y; dst[6]=b.z;  dst[7]=b.w;
        dst[8]=c.x; dst[9]=c.y; dst[10]=c.z; dst[11]=c.w;
    } else {
        #pragma unroll
        for (int j = 0; j < 12; j++) {
            int cc = c0 - 4 + j;
            dst[j] = (cc >= 0 && cc < HW) ? __ldg(&x[yy * HW + cc]) : 0.0f;
        }
    }
}

__global__ __launch_bounds__(128) void blur_hist(const float* __restrict__ x,
                                                 const float* __restrict__ bk) {
    __shared__ unsigned int wh[NW1];
    __shared__ unsigned int sred[4];
    for (int i = threadIdx.x; i < NW1; i += 128) wh[i] = 0u;
    __syncthreads();

    const float w  = bk[0];
    const int   c0 = blockIdx.x * 512 + threadIdx.x * 4;
    const int   y0 = blockIdx.y * RPB;
    const int   blk = blockIdx.y * 8 + blockIdx.x;
    const bool  safe = (c0 >= 4) && (c0 <= HW - 9);
    const int   lane = threadIdx.x & 31;
    unsigned int cntAbove = 0;

    float f[5][12];
    #pragma unroll
    for (int i = 0; i < 4; i++) load_row(f[i], x, y0 - 2 + i, c0, safe);

    #pragma unroll
    for (int k = 0; k < RPB; k++) {
        const int y = y0 + k;
        load_row(f[(k + 4) % 5], x, y + 2, c0, safe);

        float4 o;
        float* op = (float*)&o;
        #pragma unroll
        for (int u = 0; u < 4; u++) {
            float acc = 0.0f;
            #pragma unroll
            for (int j = 0; j < 5; j++)        // kw outer
                #pragma unroll
                for (int i = 0; i < 5; i++)    // kh inner (fastest) — Eigen order
                    acc = fmaf(f[(k + i) % 5][u + j + 2], w, acc);
            op[u] = acc;
            unsigned int key = __float_as_uint(acc);
            cntAbove += (key >= WHI) ? 1u : 0u;
            if (key - WLO < WSPAN)
                atomicAdd(&wh[(key - WLO) >> W1SHIFT], 1u);
        }
        *(float4*)&g_blur[y * HW + c0] = o;
    }

    #pragma unroll
    for (int off = 16; off; off >>= 1)
        cntAbove += __shfl_down_sync(0xffffffffu, cntAbove, off);
    if (lane == 0) sred[threadIdx.x >> 5] = cntAbove;
    __syncthreads();
    if (threadIdx.x == 0)
        g_babove[blk] = sred[0] + sred[1] + sred[2] + sred[3];
    for (int i = threadIdx.x; i < NW1; i += 128)
        g_bhist[blk][i] = wh[i];
}

// ---------------- warp inclusive suffix sum (lane..31) ----------------
__device__ __forceinline__ unsigned int warp_suffix(unsigned int v, int lane) {
    #pragma unroll
    for (int off = 1; off < 32; off <<= 1) {
        unsigned int u = __shfl_down_sync(0xffffffffu, v, off);
        if (lane + off < 32) v += u;
    }
    return v;
}

// ---------------- K2: sum block hists, locate level-1 bins (2-barrier scan) -------------
__global__ __launch_bounds__(1024) void coarse_select_win() {
    __shared__ unsigned int ws[32];
    __shared__ unsigned int sw[32];
    __shared__ unsigned int sga;
    const int p = blockIdx.x, t = threadIdx.x;
    const int lane = t & 31, wid = t >> 5;
    const int pr = p >> 3, pc = p & 7;

    // zero the sub-hist for this patch (runs before refine_pass)
    g_sub[p][0][t] = 0u;
    g_sub[p][1][t] = 0u;

    // sum the per-block hists (bins >= NW1 are zero)
    unsigned int c = 0;
    if (t < NW1) {
        #pragma unroll 4
        for (int s = 0; s < BPPY; s++)
            c += g_bhist[(pr * BPPY + s) * 8 + pc][t];
    }
    unsigned int s = warp_suffix(c, lane);
    if (lane == 0) ws[wid] = s;

    if (wid == 1) {  // warp 1 also sums the per-block above-counts (BPPY = 32)
        unsigned int a = g_babove[(pr * BPPY + lane) * 8 + pc];
        #pragma unroll
        for (int off = 16; off; off >>= 1)
            a += __shfl_down_sync(0xffffffffu, a, off);
        if (lane == 0) sga = a;
    }
    __syncthreads();
    if (wid == 0) sw[lane] = warp_suffix(ws[lane], lane);
    __syncthreads();

    const unsigned int ga = sga;
    const unsigned int total_in = sw[0];
    unsigned int above = (s - c) + ((wid < 31) ? sw[wid + 1] : 0u) + ga;

    if (t == 0)
        g_need[p] = (ga >= K2) || (ga + total_in < K1) ? 1 : 0;

    if (above < K1 && K1 <= above + c) { g_sel[p][0] = (unsigned)t; g_sel[p][1] = above; }
    if (above < K2 && K2 <= above + c) { g_sel[p][2] = (unsigned)t; g_sel[p][3] = above; }
}

// ---------------- K3a: sub-histogram, full re-read of g_blur (4x float4/iter) --------------
__global__ __launch_bounds__(256) void refine_pass() {
    __shared__ unsigned int sbin[NPATCH][2];
    if (threadIdx.x < NPATCH) {
        sbin[threadIdx.x][0] = g_sel[threadIdx.x][0];
        sbin[threadIdx.x][1] = g_sel[threadIdx.x][2];
    }
    __syncthreads();
    const float4* b4 = (const float4*)g_blur;
    const unsigned int stride = gridDim.x * 256;   // 524288; NPIX/4/stride = 8 exactly
    const unsigned int i0 = blockIdx.x * 256 + threadIdx.x;
    #pragma unroll
    for (int rep = 0; rep < 2; rep++) {
        unsigned int base = i0 + rep * 4 * stride;
        float4 v0 = __ldg(&b4[base]);
        float4 v1 = __ldg(&b4[base + stride]);
        float4 v2 = __ldg(&b4[base + 2 * stride]);
        float4 v3 = __ldg(&b4[base + 3 * stride]);
        #pragma unroll
        for (int h = 0; h < 4; h++) {
            unsigned int ii = base + h * stride;
            const float4& vv = h == 0 ? v0 : h == 1 ? v1 : h == 2 ? v2 : v3;
            const float* vp = (const float*)&vv;
            int y = ii >> 10;
            int p = ((y >> 9) << 3) + ((ii & 1023u) >> 7);
            #pragma unroll
            for (int u = 0; u < 4; u++) {
                unsigned int wk = __float_as_uint(vp[u]) - WLO;
                if (wk < WSPAN) {
                    unsigned int bin = wk >> W1SHIFT;
                    if (bin == sbin[p][0]) atomicAdd(&g_sub[p][0][wk & 1023u], 1u);
                    if (bin == sbin[p][1]) atomicAdd(&g_sub[p][1][wk & 1023u], 1u);
                }
            }
        }
    }
}

// ---------------- walk (bit-faithful; branch-free 16-step batches) ----------------
// Reference semantics: while (A <= th) th -= 0.0005f;  stop at first value with A > th.
// The 16 FADDs form a pure dependent chain; predicates/selects are off-chain; ONE
// branch per batch. Monotonicity => lowest set mask bit is the reference stop point.
__device__ __forceinline__ float walk_down(float th, float A) {
    if (!(A <= th)) return th;
    for (int g = 0; g < 1300; g++) {
        float t1  = th  - 0.0005f;  float t2  = t1  - 0.0005f;
        float t3  = t2  - 0.0005f;  float t4  = t3  - 0.0005f;
        float t5  = t4  - 0.0005f;  float t6  = t5  - 0.0005f;
        float t7  = t6  - 0.0005f;  float t8  = t7  - 0.0005f;
        float t9  = t8  - 0.0005f;  float t10 = t9  - 0.0005f;
        float t11 = t10 - 0.0005f;  float t12 = t11 - 0.0005f;
        float t13 = t12 - 0.0005f;  float t14 = t13 - 0.0005f;
        float t15 = t14 - 0.0005f;  float t16 = t15 - 0.0005f;
        unsigned int m = 0;
        m |= (A > t1)  ? 1u << 0  : 0u;  m |= (A > t2)  ? 1u << 1  : 0u;
        m |= (A > t3)  ? 1u << 2  : 0u;  m |= (A > t4)  ? 1u << 3  : 0u;
        m |= (A > t5)  ? 1u << 4  : 0u;  m |= (A > t6)  ? 1u << 5  : 0u;
        m |= (A > t7)  ? 1u << 6  : 0u;  m |= (A > t8)  ? 1u << 7  : 0u;
        m |= (A > t9)  ? 1u << 8  : 0u;  m |= (A > t10) ? 1u << 9  : 0u;
        m |= (A > t11) ? 1u << 10 : 0u;  m |= (A > t12) ? 1u << 11 : 0u;
        m |= (A > t13) ? 1u << 12 : 0u;  m |= (A > t14) ? 1u << 13 : 0u;
        m |= (A > t15) ? 1u << 14 : 0u;  m |= (A > t16) ? 1u << 15 : 0u;
        if (m) {   // pick lowest set bit via predicated selects
            float sel = t16;
            sel = (m & (1u << 14)) ? t15 : sel;  sel = (m & (1u << 13)) ? t14 : sel;
            sel = (m & (1u << 12)) ? t13 : sel;  sel = (m & (1u << 11)) ? t12 : sel;
            sel = (m & (1u << 10)) ? t11 : sel;  sel = (m & (1u << 9))  ? t10 : sel;
            sel = (m & (1u << 8))  ? t9  : sel;  sel = (m & (1u << 7))  ? t8  : sel;
            sel = (m & (1u << 6))  ? t7  : sel;  sel = (m & (1u << 5))  ? t6  : sel;
            sel = (m & (1u << 4))  ? t5  : sel;  sel = (m & (1u << 3))  ? t4  : sel;
            sel = (m & (1u << 2))  ? t3  : sel;  sel = (m & (1u << 1))  ? t2  : sel;
            sel = (m & (1u << 0))  ? t1  : sel;
            return sel;
        }
        th = t16;
    }
    return th;
}
// Reference: while (B > th) th += 0.0005f;  stop at first value with B <= th.
__device__ __forceinline__ float walk_up(float th, float B) {
    if (!(B > th)) return th;
    for (int g = 0; g < 1300; g++) {
        float t1  = th  + 0.0005f;  float t2  = t1  + 0.0005f;
        float t3  = t2  + 0.0005f;  float t4  = t3  + 0.0005f;
        float t5  = t4  + 0.0005f;  float t6  = t5  + 0.0005f;
        float t7  = t6  + 0.0005f;  float t8  = t7  + 0.0005f;
        float t9  = t8  + 0.0005f;  float t10 = t9  + 0.0005f;
        float t11 = t10 + 0.0005f;  float t12 = t11 + 0.0005f;
        float t13 = t12 + 0.0005f;  float t14 = t13 + 0.0005f;
        float t15 = t14 + 0.0005f;  float t16 = t15 + 0.0005f;
        unsigned int m = 0;
        m |= (B <= t1)  ? 1u << 0  : 0u;  m |= (B <= t2)  ? 1u << 1  : 0u;
        m |= (B <= t3)  ? 1u << 2  : 0u;  m |= (B <= t4)  ? 1u << 3  : 0u;
        m |= (B <= t5)  ? 1u << 4  : 0u;  m |= (B <= t6)  ? 1u << 5  : 0u;
        m |= (B <= t7)  ? 1u << 6  : 0u;  m |= (B <= t8)  ? 1u << 7  : 0u;
        m |= (B <= t9)  ? 1u << 8  : 0u;  m |= (B <= t10) ? 1u << 9  : 0u;
        m |= (B <= t11) ? 1u << 10 : 0u;  m |= (B <= t12) ? 1u << 11 : 0u;
        m |= (B <= t13) ? 1u << 12 : 0u;  m |= (B <= t14) ? 1u << 13 : 0u;
        m |= (B <= t15) ? 1u << 14 : 0u;  m |= (B <= t16) ? 1u << 15 : 0u;
        if (m) {
            float sel = t16;
            sel = (m & (1u << 14)) ? t15 : sel;  sel = (m & (1u << 13)) ? t14 : sel;
            sel = (m & (1u << 12)) ? t13 : sel;  sel = (m & (1u << 11)) ? t12 : sel;
            sel = (m & (1u << 10)) ? t11 : sel;  sel = (m & (1u << 9))  ? t10 : sel;
            sel = (m & (1u << 8))  ? t9  : sel;  sel = (m & (1u << 7))  ? t8  : sel;
            sel = (m & (1u << 6))  ? t7  : sel;  sel = (m & (1u << 5))  ? t6  : sel;
            sel = (m & (1u << 4))  ? t5  : sel;  sel = (m & (1u << 3))  ? t4  : sel;
            sel = (m & (1u << 2))  ? t3  : sel;  sel = (m & (1u << 1))  ? t2  : sel;
            sel = (m & (1u << 0))  ? t1  : sel;
            return sel;
        }
        th = t16;
    }
    return th;
}

// ---------------- K3b: exact key within level-1 bin (+ fallback) + fused walk -------------
__global__ __launch_bounds__(1024) void refine_select_fb() {
    __shared__ unsigned int ws[32];
    __shared__ unsigned int sw[32];
    __shared__ unsigned int scnt;
    __shared__ int slast;
    __shared__ unsigned int skey[NPATCH][2];
    const int p = blockIdx.x, t = threadIdx.x;
    const int lane = t & 31, wid = t >> 5;

    if (!g_need[p]) {
        for (int q = 0; q < 2; q++) {
            const unsigned int bin = g_sel[p][q * 2];
            const unsigned int ab  = g_sel[p][q * 2 + 1];
            const unsigned int r   = (q ? K2 : K1) - ab;

            unsigned int c = g_sub[p][q][t];
            unsigned int s = warp_suffix(c, lane);
            if (lane == 0) ws[wid] = s;
            __syncthreads();
            if (wid == 0) sw[lane] = warp_suffix(ws[lane], lane);
            if (t == 0) g_key[p][q] = WLO + (bin << W1SHIFT);
            __syncthreads();
            unsigned int above = (s - c) + ((wid < 31) ? sw[wid + 1] : 0u);
            if (above < r && r <= above + c)
                g_key[p][q] = WLO + (bin << W1SHIFT) + (unsigned)t;
            __syncthreads();
        }
    } else {
        // exact fallback: binary search on the key over the whole patch
        const float* base = g_blur + ((p >> 3) * 512) * HW + (p & 7) * 512;
        for (int q = 0; q < 2; q++) {
            const unsigned int K = q ? K2 : K1;
            unsigned int lo = 0u, hi = 0x40000000u;
            while (hi - lo > 1u) {
                unsigned int mid = lo + ((hi - lo) >> 1);
                unsigned int cnt = 0;
                for (int i = t; i < 512 * 512; i += 1024) {
                    unsigned int key = __float_as_uint(base[(i >> 9) * HW + (i & 511)]);
                    cnt += (key >= mid) ? 1u : 0u;
                }
                #pragma unroll
                for (int off = 16; off; off >>= 1)
                    cnt += __shfl_down_sync(0xffffffffu, cnt, off);
                if (lane == 0) ws[wid] = cnt;
                __syncthreads();
                if (t == 0) {
                    unsigned int s = 0;
                    for (int i = 0; i < 32; i++) s += ws[i];
                    scnt = s;
                }
                __syncthreads();
                if (scnt >= K) lo = mid; else hi = mid;
                __syncthreads();
            }
            if (t == 0) g_key[p][q] = lo;
            __syncthreads();
        }
    }

    // ---- fused walk: last block runs the serial threshold walk ----
    __syncthreads();
    __threadfence();
    if (t == 0)
        slast = (atomicAdd(&g_done, 1u) == NPATCH - 1) ? 1 : 0;
    __syncthreads();
    if (slast) {
        if (t < NPATCH) {   // parallel key preload (MLP across 64 threads)
            skey[t][0] = *((volatile unsigned int*)&g_key[t][0]);
            skey[t][1] = *((volatile unsigned int*)&g_key[t][1]);
        }
        __syncthreads();
        if (t == 0) {
            float th = 0.5f;
            for (int pp = 0; pp < NPATCH; pp++) {
                float A = __uint_as_float(skey[pp][0]);
                float B = __uint_as_float(skey[pp][1]);
                th = walk_down(th, A);
                th = walk_up(th, B);
                g_th[pp] = th;
            }
            __threadfence();
            g_done = 0;   // reset for graph replay determinism
        }
    }
}

// ---------------- K5: bit-packed binarize + close (dilate5, erode5) ----------------
#define CTW  256
#define CTH  128
#define WPR  10
#define TROWS 136
__global__ __launch_bounds__(256) void close_k(float* __restrict__ out) {
    __shared__ unsigned int A[TROWS][WPR];
    __shared__ unsigned int B[TROWS][WPR];
    __shared__ float sth[NPATCH];
    const int t = threadIdx.x;
    if (t < NPATCH) sth[t] = g_th[t];
    __syncthreads();

    const int gx0 = blockIdx.x * CTW;
    const int gy0 = blockIdx.y * CTH;
    const int lane = t & 31, wid = t >> 5;
    const bool xsafe = (gx0 >= 32) && (gx0 + CTW + 32 <= HW);

    // binarize -> packed words
    for (int rr = 0; rr < TROWS / 8; rr++) {       // 17 rows per warp
        const int r  = wid + rr * 8;
        const int gy = gy0 + r - 4;
        const bool gyok = (unsigned)gy < HW;
        if (xsafe && gyok) {
            const float4* rowp = (const float4*)(g_blur + (size_t)gy * HW + (gx0 - 32));
            const int prow = (gy >> 9) << 3;
            #pragma unroll
            for (int ch = 0; ch < 2; ch++) {
                float4 a = rowp[ch * 32 + lane];
                int gx = gx0 - 32 + ch * 128 + lane * 4;
                float th = sth[prow + (gx >> 9)];
                unsigned int nib = (unsigned)(a.x > th) | ((unsigned)(a.y > th) << 1)
                                 | ((unsigned)(a.z > th) << 2) | ((unsigned)(a.w > th) << 3);
                unsigned int comb = nib << ((lane & 7) * 4);
                comb |= __shfl_xor_sync(0xffffffffu, comb, 1);
                comb |= __shfl_xor_sync(0xffffffffu, comb, 2);
                comb |= __shfl_xor_sync(0xffffffffu, comb, 4);
                if ((lane & 7) == 0) A[r][ch * 4 + (lane >> 3)] = comb;
            }
            if (lane < 16) {
                float4 a = rowp[64 + lane];
                int gx = gx0 - 32 + 256 + lane * 4;
                float th = sth[prow + (gx >> 9)];
                unsigned int nib = (unsigned)(a.x > th) | ((unsigned)(a.y > th) << 1)
                                 | ((unsigned)(a.z > th) << 2) | ((unsigned)(a.w > th) << 3);
                unsigned int comb = nib << ((lane & 7) * 4);
                comb |= __shfl_xor_sync(0x0000ffffu, comb, 1);
                comb |= __shfl_xor_sync(0x0000ffffu, comb, 2);
                comb |= __shfl_xor_sync(0x0000ffffu, comb, 4);
                if ((lane & 7) == 0) A[r][8 + (lane >> 3)] = comb;
            }
        } else if (!gyok) {
            if (lane < WPR) A[r][lane] = 0u;
        } else {
            float v[WPR];
            #pragma unroll
            for (int wc = 0; wc < WPR; wc++) {
                int gx = gx0 + (wc - 1) * 32 + lane;
                v[wc] = ((unsigned)gx < HW) ? g_blur[(size_t)gy * HW + gx] : 0.0f;
            }
            #pragma unroll
            for (int wc = 0; wc < WPR; wc++) {
                int gx = gx0 + (wc - 1) * 32 + lane;
                unsigned int bit = 0;
                if ((unsigned)gx < HW)
                    bit = (v[wc] > sth[((gy >> 9) << 3) + (gx >> 9)]) ? 1u : 0u;
                unsigned int word = __ballot_sync(0xffffffffu, bit);
                if (lane == 0) A[r][wc] = word;
            }
        }
    }
    __syncthreads();

    for (int i = t; i < TROWS * WPR; i += 256) {
        int r = i / WPR, wc = i % WPR;
        unsigned int wv = A[r][wc];
        unsigned int lw = wc > 0       ? A[r][wc - 1] : 0u;
        unsigned int rw = wc < WPR - 1 ? A[r][wc + 1] : 0u;
        B[r][wc] = wv | __funnelshift_r(wv, rw, 1) | __funnelshift_r(wv, rw, 2)
                      | __funnelshift_l(lw, wv, 1) | __funnelshift_l(lw, wv, 2);
    }
    __syncthreads();

    for (int i = t; i < TROWS * WPR; i += 256) {
        int r = i / WPR, wc = i % WPR;
        unsigned int d = 0u;
        if (r >= 2 && r < TROWS - 2)
            d = B[r-2][wc] | B[r-1][wc] | B[r][wc] | B[r+1][wc] | B[r+2][wc];
        int gy = gy0 + r - 4;
        bool xout = (wc == 0 && gx0 == 0) || (wc == WPR - 1 && gx0 + CTW == HW);
        if ((unsigned)gy >= HW || xout) d = 0xffffffffu;
        A[r][wc] = d;
    }
    __syncthreads();

    for (int i = t; i < TROWS * WPR; i += 256) {
        int r = i / WPR, wc = i % WPR;
        unsigned int wv = A[r][wc];
        unsigned int lw = wc > 0       ? A[r][wc - 1] : 0xffffffffu;
        unsigned int rw = wc < WPR - 1 ? A[r][wc + 1] : 0xffffffffu;
        B[r][wc] = wv & __funnelshift_r(wv, rw, 1) & __funnelshift_r(wv, rw, 2)
                      & __funnelshift_l(lw, wv, 1) & __funnelshift_l(lw, wv, 2);
    }
    __syncthreads();

    for (int i = t; i < CTH * 8; i += 256) {
        int r = (i >> 3) + 4, wc = (i & 7) + 1;
        unsigned int v = B[r-2][wc] & B[r-1][wc] & B[r][wc] & B[r+1][wc] & B[r+2][wc];
        int gy = gy0 + r - 4;
        int gx = gx0 + (wc - 1) * 32;
        float4* o = (float4*)&out[(size_t)gy * HW + gx];
        #pragma unroll
        for (int q = 0; q < 8; q++) {
            float4 fv;
            fv.x = (v >> (q * 4 + 0)) & 1u ? 1.0f : 0.0f;
            fv.y = (v >> (q * 4 + 1)) & 1u ? 1.0f : 0.0f;
            fv.z = (v >> (q * 4 + 2)) & 1u ? 1.0f : 0.0f;
            fv.w = (v >> (q * 4 + 3)) & 1u ? 1.0f : 0.0f;
            o[q] = fv;
        }
    }
}

// ---------------- launch ----------------
extern "C" void kernel_launch(void* const* d_in, const int* in_sizes, int n_in,
                              void* d_out, int out_size) {
    const float* x  = (const float*)d_in[0];
    const float* bk = (const float*)d_in[1];
    float* out = (float*)d_out;
    (void)in_sizes; (void)n_in; (void)out_size;

    blur_hist<<<dim3(HW / 512, HW / RPB), 128>>>(x, bk);
    coarse_select_win<<<NPATCH, 1024>>>();
    refine_pass<<<2048, 256>>>();
    refine_select_fb<<<NPATCH, 1024>>>();   // walk fused (last block, branch-free batches)
    close_k<<<dim3(HW / CTW, HW / CTH), 256>>>(out);
}

// round 15
// speedup vs baseline: 1.2557x; 1.0590x over previous
#include <cuda_runtime.h>

// ---------------- problem constants ----------------
#define HW      4096
#define NPIX    (HW*HW)
#define NPATCH  64
#define K1      31458u   // loop1 continues iff count(v>th) <= 31457  <=>  v_(31458) <= th
#define K2      20972u   // loop2 continues iff count(v>th) >= 20972  <=>  v_(20972) >  th

// value window (verified per-patch; exact fallback if violated)
#define WLO     0x3F0E0000u   // ~0.5547
#define WHI     0x3F1A0000u   // ~0.6016
#define WSPAN   0xC0000u
#define NW1     768           // level-1 bins of 1024 keys each
#define W1SHIFT 10

#define RPB     16            // rows per blur block
#define BPPY    (512 / RPB)   // blur blocks per patch, vertically (32)
#define NBLK    (8 * (HW / RPB))   // total blur blocks (2048)

// ---------------- device scratch ----------------
__device__ float        g_blur[NPIX];
__device__ unsigned int g_bhist[NBLK][NW1];      // per-block hist (plain stores, no zeroing)
__device__ unsigned int g_babove[NBLK];
__device__ int          g_need [NPATCH];         // exact-fallback flag (plain store)
__device__ unsigned int g_sub  [NPATCH][2][1024];
__device__ unsigned int g_sel  [NPATCH][4];      // bin1, above1, bin2, above2
__device__ unsigned int g_key  [NPATCH][2];
__device__ float        g_th   [NPATCH];
__device__ unsigned int g_done = 0;              // last-block counter (reset after use)

// ---------------- K1: blur (circular register window, fully unrolled) + per-block hist ----
// Per-pixel 25-tap fmaf chain IDENTICAL to the passing version (kw outer, kh inner).
__device__ __forceinline__ void load_row(float* dst, const float* __restrict__ x,
                                         int yy, int c0, bool safe) {
    if (yy < 0 || yy >= HW) {
        #pragma unroll
        for (int j = 0; j < 12; j++) dst[j] = 0.0f;
    } else if (safe) {
        const float4* p = (const float4*)&x[yy * HW + c0 - 4];
        float4 a = __ldg(p), b = __ldg(p + 1), c = __ldg(p + 2);
        dst[0]=a.x; dst[1]=a.y; dst[2]=a.z;  dst[3]=a.w;
        dst[4]=b.x; dst[5]=b.y; dst[6]=b.z;  dst[7]=b.w;
        dst[8]=c.x; dst[9]=c.y; dst[10]=c.z; dst[11]=c.w;
    } else {
        #pragma unroll
        for (int j = 0; j < 12; j++) {
            int cc = c0 - 4 + j;
            dst[j] = (cc >= 0 && cc < HW) ? __ldg(&x[yy * HW + cc]) : 0.0f;
        }
    }
}

__global__ __launch_bounds__(128) void blur_hist(const float* __restrict__ x,
                                                 const float* __restrict__ bk) {
    __shared__ unsigned int wh[NW1];
    __shared__ unsigned int sred[4];
    for (int i = threadIdx.x; i < NW1; i += 128) wh[i] = 0u;
    __syncthreads();

    const float w  = bk[0];
    const int   c0 = blockIdx.x * 512 + threadIdx.x * 4;
    const int   y0 = blockIdx.y * RPB;
    const int   blk = blockIdx.y * 8 + blockIdx.x;
    const bool  safe = (c0 >= 4) && (c0 <= HW - 9);
    const int   lane = threadIdx.x & 31;
    unsigned int cntAbove = 0;

    float f[5][12];
    #pragma unroll
    for (int i = 0; i < 4; i++) load_row(f[i], x, y0 - 2 + i, c0, safe);

    #pragma unroll
    for (int k = 0; k < RPB; k++) {
        const int y = y0 + k;
        load_row(f[(k + 4) % 5], x, y + 2, c0, safe);

        float4 o;
        float* op = (float*)&o;
        #pragma unroll
        for (int u = 0; u < 4; u++) {
            float acc = 0.0f;
            #pragma unroll
            for (int j = 0; j < 5; j++)        // kw outer
                #pragma unroll
                for (int i = 0; i < 5; i++)    // kh inner (fastest) — Eigen order
                    acc = fmaf(f[(k + i) % 5][u + j + 2], w, acc);
            op[u] = acc;
            unsigned int key = __float_as_uint(acc);
            cntAbove += (key >= WHI) ? 1u : 0u;
            if (key - WLO < WSPAN)
                atomicAdd(&wh[(key - WLO) >> W1SHIFT], 1u);
        }
        *(float4*)&g_blur[y * HW + c0] = o;
    }

    #pragma unroll
    for (int off = 16; off; off >>= 1)
        cntAbove += __shfl_down_sync(0xffffffffu, cntAbove, off);
    if (lane == 0) sred[threadIdx.x >> 5] = cntAbove;
    __syncthreads();
    if (threadIdx.x == 0)
        g_babove[blk] = sred[0] + sred[1] + sred[2] + sred[3];
    for (int i = threadIdx.x; i < NW1; i += 128)
        g_bhist[blk][i] = wh[i];
}

// ---------------- warp inclusive suffix sum (lane..31) ----------------
__device__ __forceinline__ unsigned int warp_suffix(unsigned int v, int lane) {
    #pragma unroll
    for (int off = 1; off < 32; off <<= 1) {
        unsigned int u = __shfl_down_sync(0xffffffffu, v, off);
        if (lane + off < 32) v += u;
    }
    return v;
}

// ---------------- K2: sum block hists, locate level-1 bins (2-barrier scan) -------------
__global__ __launch_bounds__(1024) void coarse_select_win() {
    __shared__ unsigned int ws[32];
    __shared__ unsigned int sw[32];
    __shared__ unsigned int sga;
    const int p = blockIdx.x, t = threadIdx.x;
    const int lane = t & 31, wid = t >> 5;
    const int pr = p >> 3, pc = p & 7;

    // zero the sub-hist for this patch (runs before refine_pass)
    g_sub[p][0][t] = 0u;
    g_sub[p][1][t] = 0u;

    // sum the per-block hists (bins >= NW1 are zero)
    unsigned int c = 0;
    if (t < NW1) {
        #pragma unroll 4
        for (int s = 0; s < BPPY; s++)
            c += g_bhist[(pr * BPPY + s) * 8 + pc][t];
    }
    unsigned int s = warp_suffix(c, lane);
    if (lane == 0) ws[wid] = s;

    if (wid == 1) {  // warp 1 also sums the per-block above-counts (BPPY = 32)
        unsigned int a = g_babove[(pr * BPPY + lane) * 8 + pc];
        #pragma unroll
        for (int off = 16; off; off >>= 1)
            a += __shfl_down_sync(0xffffffffu, a, off);
        if (lane == 0) sga = a;
    }
    __syncthreads();
    if (wid == 0) sw[lane] = warp_suffix(ws[lane], lane);
    __syncthreads();

    const unsigned int ga = sga;
    const unsigned int total_in = sw[0];
    unsigned int above = (s - c) + ((wid < 31) ? sw[wid + 1] : 0u) + ga;

    if (t == 0)
        g_need[p] = (ga >= K2) || (ga + total_in < K1) ? 1 : 0;

    if (above < K1 && K1 <= above + c) { g_sel[p][0] = (unsigned)t; g_sel[p][1] = above; }
    if (above < K2 && K2 <= above + c) { g_sel[p][2] = (unsigned)t; g_sel[p][3] = above; }
}

// ---------------- K3a: sub-histogram, full re-read of g_blur (4x float4/iter) --------------
__global__ __launch_bounds__(256) void refine_pass() {
    __shared__ unsigned int sbin[NPATCH][2];
    if (threadIdx.x < NPATCH) {
        sbin[threadIdx.x][0] = g_sel[threadIdx.x][0];
        sbin[threadIdx.x][1] = g_sel[threadIdx.x][2];
    }
    __syncthreads();
    const float4* b4 = (const float4*)g_blur;
    const unsigned int stride = gridDim.x * 256;   // 524288; NPIX/4/stride = 8 exactly
    const unsigned int i0 = blockIdx.x * 256 + threadIdx.x;
    #pragma unroll
    for (int rep = 0; rep < 2; rep++) {
        unsigned int base = i0 + rep * 4 * stride;
        float4 v0 = __ldg(&b4[base]);
        float4 v1 = __ldg(&b4[base + stride]);
        float4 v2 = __ldg(&b4[base + 2 * stride]);
        float4 v3 = __ldg(&b4[base + 3 * stride]);
        #pragma unroll
        for (int h = 0; h < 4; h++) {
            unsigned int ii = base + h * stride;
            const float4& vv = h == 0 ? v0 : h == 1 ? v1 : h == 2 ? v2 : v3;
            const float* vp = (const float*)&vv;
            int y = ii >> 10;
            int p = ((y >> 9) << 3) + ((ii & 1023u) >> 7);
            #pragma unroll
            for (int u = 0; u < 4; u++) {
                unsigned int wk = __float_as_uint(vp[u]) - WLO;
                if (wk < WSPAN) {
                    unsigned int bin = wk >> W1SHIFT;
                    if (bin == sbin[p][0]) atomicAdd(&g_sub[p][0][wk & 1023u], 1u);
                    if (bin == sbin[p][1]) atomicAdd(&g_sub[p][1][wk & 1023u], 1u);
                }
            }
        }
    }
}

// ---------------- walk (bit-faithful; lean 16-FADD batches, binary-search select) -------
// Reference: while (A <= th) th -= 0.0005f; stop at first t with A > t.
// Loop invariant on entry to each batch: A <= th. Monotone decreasing t_i means the
// batch contains the stop iff A > t16; the stop index is found by binary search
// (pred-as-data SELs, off the hot path). Identical float sequence + stop condition.
__device__ __forceinline__ float walk_down(float th, float A) {
    if (!(A <= th)) return th;
    for (int g = 0; g < 1300; g++) {
        float t1  = th  - 0.0005f;  float t2  = t1  - 0.0005f;
        float t3  = t2  - 0.0005f;  float t4  = t3  - 0.0005f;
        float t5  = t4  - 0.0005f;  float t6  = t5  - 0.0005f;
        float t7  = t6  - 0.0005f;  float t8  = t7  - 0.0005f;
        float t9  = t8  - 0.0005f;  float t10 = t9  - 0.0005f;
        float t11 = t10 - 0.0005f;  float t12 = t11 - 0.0005f;
        float t13 = t12 - 0.0005f;  float t14 = t13 - 0.0005f;
        float t15 = t14 - 0.0005f;  float t16 = t15 - 0.0005f;
        if (A > t16) {   // stop is inside this batch: binary search (monotone)
            float r;
            if (A > t8)
                r = (A > t4) ? ((A > t2) ? ((A > t1) ? t1 : t2) : ((A > t3) ? t3 : t4))
                             : ((A > t6) ? ((A > t5) ? t5 : t6) : ((A > t7) ? t7 : t8));
            else
                r = (A > t12) ? ((A > t10) ? ((A > t9)  ? t9  : t10) : ((A > t11) ? t11 : t12))
                              : ((A > t14) ? ((A > t13) ? t13 : t14) : ((A > t15) ? t15 : t16));
            return r;
        }
        th = t16;
    }
    return th;
}
// Reference: while (B > th) th += 0.0005f; stop at first t with B <= t.
__device__ __forceinline__ float walk_up(float th, float B) {
    if (!(B > th)) return th;
    for (int g = 0; g < 1300; g++) {
        float t1  = th  + 0.0005f;  float t2  = t1  + 0.0005f;
        float t3  = t2  + 0.0005f;  float t4  = t3  + 0.0005f;
        float t5  = t4  + 0.0005f;  float t6  = t5  + 0.0005f;
        float t7  = t6  + 0.0005f;  float t8  = t7  + 0.0005f;
        float t9  = t8  + 0.0005f;  float t10 = t9  + 0.0005f;
        float t11 = t10 + 0.0005f;  float t12 = t11 + 0.0005f;
        float t13 = t12 + 0.0005f;  float t14 = t13 + 0.0005f;
        float t15 = t14 + 0.0005f;  float t16 = t15 + 0.0005f;
        if (B <= t16) {  // stop inside batch: monotone increasing, binary search
            float r;
            if (B <= t8)
                r = (B <= t4) ? ((B <= t2) ? ((B <= t1) ? t1 : t2) : ((B <= t3) ? t3 : t4))
                              : ((B <= t6) ? ((B <= t5) ? t5 : t6) : ((B <= t7) ? t7 : t8));
            else
                r = (B <= t12) ? ((B <= t10) ? ((B <= t9)  ? t9  : t10) : ((B <= t11) ? t11 : t12))
                               : ((B <= t14) ? ((B <= t13) ? t13 : t14) : ((B <= t15) ? t15 : t16));
            return r;
        }
        th = t16;
    }
    return th;
}

// ---------------- K3b: exact key within level-1 bin (+ fallback) + fused walk -------------
__global__ __launch_bounds__(1024) void refine_select_fb() {
    __shared__ unsigned int ws[32];
    __shared__ unsigned int sw[32];
    __shared__ unsigned int scnt;
    __shared__ int slast;
    __shared__ unsigned int skey[NPATCH][2];
    const int p = blockIdx.x, t = threadIdx.x;
    const int lane = t & 31, wid = t >> 5;

    if (!g_need[p]) {
        for (int q = 0; q < 2; q++) {
            const unsigned int bin = g_sel[p][q * 2];
            const unsigned int ab  = g_sel[p][q * 2 + 1];
            const unsigned int r   = (q ? K2 : K1) - ab;

            unsigned int c = g_sub[p][q][t];
            unsigned int s = warp_suffix(c, lane);
            if (lane == 0) ws[wid] = s;
            __syncthreads();
            if (wid == 0) sw[lane] = warp_suffix(ws[lane], lane);
            if (t == 0) g_key[p][q] = WLO + (bin << W1SHIFT);
            __syncthreads();
            unsigned int above = (s - c) + ((wid < 31) ? sw[wid + 1] : 0u);
            if (above < r && r <= above + c)
                g_key[p][q] = WLO + (bin << W1SHIFT) + (unsigned)t;
            __syncthreads();
        }
    } else {
        // exact fallback: binary search on the key over the whole patch
        const float* base = g_blur + ((p >> 3) * 512) * HW + (p & 7) * 512;
        for (int q = 0; q < 2; q++) {
            const unsigned int K = q ? K2 : K1;
            unsigned int lo = 0u, hi = 0x40000000u;
            while (hi - lo > 1u) {
                unsigned int mid = lo + ((hi - lo) >> 1);
                unsigned int cnt = 0;
                for (int i = t; i < 512 * 512; i += 1024) {
                    unsigned int key = __float_as_uint(base[(i >> 9) * HW + (i & 511)]);
                    cnt += (key >= mid) ? 1u : 0u;
                }
                #pragma unroll
                for (int off = 16; off; off >>= 1)
                    cnt += __shfl_down_sync(0xffffffffu, cnt, off);
                if (lane == 0) ws[wid] = cnt;
                __syncthreads();
                if (t == 0) {
                    unsigned int s = 0;
                    for (int i = 0; i < 32; i++) s += ws[i];
                    scnt = s;
                }
                __syncthreads();
                if (scnt >= K) lo = mid; else hi = mid;
                __syncthreads();
            }
            if (t == 0) g_key[p][q] = lo;
            __syncthreads();
        }
    }

    // ---- fused walk: last block runs the serial threshold walk ----
    __syncthreads();
    __threadfence();
    if (t == 0)
        slast = (atomicAdd(&g_done, 1u) == NPATCH - 1) ? 1 : 0;
    __syncthreads();
    if (slast) {
        if (t < NPATCH) {   // parallel key preload (MLP across 64 threads)
            skey[t][0] = *((volatile unsigned int*)&g_key[t][0]);
            skey[t][1] = *((volatile unsigned int*)&g_key[t][1]);
        }
        __syncthreads();
        if (t == 0) {
            float th = 0.5f;
            for (int pp = 0; pp < NPATCH; pp++) {
                float A = __uint_as_float(skey[pp][0]);
                float B = __uint_as_float(skey[pp][1]);
                th = walk_down(th, A);
                th = walk_up(th, B);
                g_th[pp] = th;
            }
            __threadfence();
            g_done = 0;   // reset for graph replay determinism
        }
    }
}

// ---------------- K5: bit-packed binarize + close (dilate5, erode5) ----------------
#define CTW  256
#define CTH  128
#define WPR  10
#define TROWS 136
__global__ __launch_bounds__(256) void close_k(float* __restrict__ out) {
    __shared__ unsigned int A[TROWS][WPR];
    __shared__ unsigned int B[TROWS][WPR];
    __shared__ float sth[NPATCH];
    const int t = threadIdx.x;
    if (t < NPATCH) sth[t] = g_th[t];
    __syncthreads();

    const int gx0 = blockIdx.x * CTW;
    const int gy0 = blockIdx.y * CTH;
    const int lane = t & 31, wid = t >> 5;
    const bool xsafe = (gx0 >= 32) && (gx0 + CTW + 32 <= HW);

    // binarize -> packed words
    for (int rr = 0; rr < TROWS / 8; rr++) {       // 17 rows per warp
        const int r  = wid + rr * 8;
        const int gy = gy0 + r - 4;
        const bool gyok = (unsigned)gy < HW;
        if (xsafe && gyok) {
            const float4* rowp = (const float4*)(g_blur + (size_t)gy * HW + (gx0 - 32));
            const int prow = (gy >> 9) << 3;
            #pragma unroll
            for (int ch = 0; ch < 2; ch++) {
                float4 a = rowp[ch * 32 + lane];
                int gx = gx0 - 32 + ch * 128 + lane * 4;
                float th = sth[prow + (gx >> 9)];
                unsigned int nib = (unsigned)(a.x > th) | ((unsigned)(a.y > th) << 1)
                                 | ((unsigned)(a.z > th) << 2) | ((unsigned)(a.w > th) << 3);
                unsigned int comb = nib << ((lane & 7) * 4);
                comb |= __shfl_xor_sync(0xffffffffu, comb, 1);
                comb |= __shfl_xor_sync(0xffffffffu, comb, 2);
                comb |= __shfl_xor_sync(0xffffffffu, comb, 4);
                if ((lane & 7) == 0) A[r][ch * 4 + (lane >> 3)] = comb;
            }
            if (lane < 16) {
                float4 a = rowp[64 + lane];
                int gx = gx0 - 32 + 256 + lane * 4;
                float th = sth[prow + (gx >> 9)];
                unsigned int nib = (unsigned)(a.x > th) | ((unsigned)(a.y > th) << 1)
                                 | ((unsigned)(a.z > th) << 2) | ((unsigned)(a.w > th) << 3);
                unsigned int comb = nib << ((lane & 7) * 4);
                comb |= __shfl_xor_sync(0x0000ffffu, comb, 1);
                comb |= __shfl_xor_sync(0x0000ffffu, comb, 2);
                comb |= __shfl_xor_sync(0x0000ffffu, comb, 4);
                if ((lane & 7) == 0) A[r][8 + (lane >> 3)] = comb;
            }
        } else if (!gyok) {
            if (lane < WPR) A[r][lane] = 0u;
        } else {
            float v[WPR];
            #pragma unroll
            for (int wc = 0; wc < WPR; wc++) {
                int gx = gx0 + (wc - 1) * 32 + lane;
                v[wc] = ((unsigned)gx < HW) ? g_blur[(size_t)gy * HW + gx] : 0.0f;
            }
            #pragma unroll
            for (int wc = 0; wc < WPR; wc++) {
                int gx = gx0 + (wc - 1) * 32 + lane;
                unsigned int bit = 0;
                if ((unsigned)gx < HW)
                    bit = (v[wc] > sth[((gy >> 9) << 3) + (gx >> 9)]) ? 1u : 0u;
                unsigned int word = __ballot_sync(0xffffffffu, bit);
                if (lane == 0) A[r][wc] = word;
            }
        }
    }
    __syncthreads();

    for (int i = t; i < TROWS * WPR; i += 256) {
        int r = i / WPR, wc = i % WPR;
        unsigned int wv = A[r][wc];
        unsigned int lw = wc > 0       ? A[r][wc - 1] : 0u;
        unsigned int rw = wc < WPR - 1 ? A[r][wc + 1] : 0u;
        B[r][wc] = wv | __funnelshift_r(wv, rw, 1) | __funnelshift_r(wv, rw, 2)
                      | __funnelshift_l(lw, wv, 1) | __funnelshift_l(lw, wv, 2);
    }
    __syncthreads();

    for (int i = t; i < TROWS * WPR; i += 256) {
        int r = i / WPR, wc = i % WPR;
        unsigned int d = 0u;
        if (r >= 2 && r < TROWS - 2)
            d = B[r-2][wc] | B[r-1][wc] | B[r][wc] | B[r+1][wc] | B[r+2][wc];
        int gy = gy0 + r - 4;
        bool xout = (wc == 0 && gx0 == 0) || (wc == WPR - 1 && gx0 + CTW == HW);
        if ((unsigned)gy >= HW || xout) d = 0xffffffffu;
        A[r][wc] = d;
    }
    __syncthreads();

    for (int i = t; i < TROWS * WPR; i += 256) {
        int r = i / WPR, wc = i % WPR;
        unsigned int wv = A[r][wc];
        unsigned int lw = wc > 0       ? A[r][wc - 1] : 0xffffffffu;
        unsigned int rw = wc < WPR - 1 ? A[r][wc + 1] : 0xffffffffu;
        B[r][wc] = wv & __funnelshift_r(wv, rw, 1) & __funnelshift_r(wv, rw, 2)
                      & __funnelshift_l(lw, wv, 1) & __funnelshift_l(lw, wv, 2);
    }
    __syncthreads();

    for (int i = t; i < CTH * 8; i += 256) {
        int r = (i >> 3) + 4, wc = (i & 7) + 1;
        unsigned int v = B[r-2][wc] & B[r-1][wc] & B[r][wc] & B[r+1][wc] & B[r+2][wc];
        int gy = gy0 + r - 4;
        int gx = gx0 + (wc - 1) * 32;
        float4* o = (float4*)&out[(size_t)gy * HW + gx];
        #pragma unroll
        for (int q = 0; q < 8; q++) {
            float4 fv;
            fv.x = (v >> (q * 4 + 0)) & 1u ? 1.0f : 0.0f;
            fv.y = (v >> (q * 4 + 1)) & 1u ? 1.0f : 0.0f;
            fv.z = (v >> (q * 4 + 2)) & 1u ? 1.0f : 0.0f;
            fv.w = (v >> (q * 4 + 3)) & 1u ? 1.0f : 0.0f;
            o[q] = fv;
        }
    }
}

// ---------------- launch ----------------
extern "C" void kernel_launch(void* const* d_in, const int* in_sizes, int n_in,
                              void* d_out, int out_size) {
    const float* x  = (const float*)d_in[0];
    const float* bk = (const float*)d_in[1];
    float* out = (float*)d_out;
    (void)in_sizes; (void)n_in; (void)out_size;

    blur_hist<<<dim3(HW / 512, HW / RPB), 128>>>(x, bk);
    coarse_select_win<<<NPATCH, 1024>>>();
    refine_pass<<<2048, 256>>>();
    refine_select_fb<<<NPATCH, 1024>>>();   // walk fused (lean batches, binary-search select)
    close_k<<<dim3(HW / CTW, HW / CTH), 256>>>(out);
}

// round 16
// speedup vs baseline: 1.2815x; 1.0205x over previous
#include <cuda_runtime.h>

// ---------------- problem constants ----------------
#define HW      4096
#define NPIX    (HW*HW)
#define NPATCH  64
#define K1      31458u   // loop1 continues iff count(v>th) <= 31457  <=>  v_(31458) <= th
#define K2      20972u   // loop2 continues iff count(v>th) >= 20972  <=>  v_(20972) >  th

// value window (verified per-patch; exact fallback if violated)
#define WLO     0x3F0E0000u   // ~0.5547
#define WHI     0x3F1A0000u   // ~0.6016
#define WSPAN   0xC0000u
#define NW1     768           // level-1 bins of 1024 keys each
#define W1SHIFT 10

#define RPB     16            // rows per blur block
#define BPPY    (512 / RPB)   // blur blocks per patch, vertically (32)
#define NBLK    (8 * (HW / RPB))   // total blur blocks (2048)

// ---------------- device scratch ----------------
__device__ float        g_blur[NPIX];
__device__ unsigned int g_bhist[NBLK][NW1];      // per-block hist (plain stores, no zeroing)
__device__ unsigned int g_babove[NBLK];
__device__ int          g_need [NPATCH];         // exact-fallback flag (plain store)
__device__ unsigned int g_sub  [NPATCH][2][1024];
__device__ unsigned int g_sel  [NPATCH][4];      // bin1, above1, bin2, above2
__device__ unsigned int g_key  [NPATCH][2];
__device__ float        g_th   [NPATCH];
__device__ unsigned int g_done = 0;              // last-block counter (reset after use)

// ---------------- K1: blur (circular register window, fully unrolled) + per-block hist ----
// Per-pixel 25-tap fmaf chain IDENTICAL to the passing version (kw outer, kh inner).
__device__ __forceinline__ void load_row(float* dst, const float* __restrict__ x,
                                         int yy, int c0, bool safe) {
    if (yy < 0 || yy >= HW) {
        #pragma unroll
        for (int j = 0; j < 12; j++) dst[j] = 0.0f;
    } else if (safe) {
        const float4* p = (const float4*)&x[yy * HW + c0 - 4];
        float4 a = __ldg(p), b = __ldg(p + 1), c = __ldg(p + 2);
        dst[0]=a.x; dst[1]=a.y; dst[2]=a.z;  dst[3]=a.w;
        dst[4]=b.x; dst[5]=b.y; dst[6]=b.z;  dst[7]=b.w;
        dst[8]=c.x; dst[9]=c.y; dst[10]=c.z; dst[11]=c.w;
    } else {
        #pragma unroll
        for (int j = 0; j < 12; j++) {
            int cc = c0 - 4 + j;
            dst[j] = (cc >= 0 && cc < HW) ? __ldg(&x[yy * HW + cc]) : 0.0f;
        }
    }
}

__global__ __launch_bounds__(128) void blur_hist(const float* __restrict__ x,
                                                 const float* __restrict__ bk) {
    __shared__ unsigned int wh[NW1];
    __shared__ unsigned int sred[4];
    for (int i = threadIdx.x; i < NW1; i += 128) wh[i] = 0u;
    __syncthreads();

    const float w  = bk[0];
    const int   c0 = blockIdx.x * 512 + threadIdx.x * 4;
    const int   y0 = blockIdx.y * RPB;
    const int   blk = blockIdx.y * 8 + blockIdx.x;
    const bool  safe = (c0 >= 4) && (c0 <= HW - 9);
    const int   lane = threadIdx.x & 31;
    unsigned int cntAbove = 0;

    float f[5][12];
    #pragma unroll
    for (int i = 0; i < 4; i++) load_row(f[i], x, y0 - 2 + i, c0, safe);

    #pragma unroll
    for (int k = 0; k < RPB; k++) {
        const int y = y0 + k;
        load_row(f[(k + 4) % 5], x, y + 2, c0, safe);

        float4 o;
        float* op = (float*)&o;
        #pragma unroll
        for (int u = 0; u < 4; u++) {
            float acc = 0.0f;
            #pragma unroll
            for (int j = 0; j < 5; j++)        // kw outer
                #pragma unroll
                for (int i = 0; i < 5; i++)    // kh inner (fastest) — Eigen order
                    acc = fmaf(f[(k + i) % 5][u + j + 2], w, acc);
            op[u] = acc;
            unsigned int key = __float_as_uint(acc);
            cntAbove += (key >= WHI) ? 1u : 0u;
            if (key - WLO < WSPAN)
                atomicAdd(&wh[(key - WLO) >> W1SHIFT], 1u);
        }
        *(float4*)&g_blur[y * HW + c0] = o;
    }

    #pragma unroll
    for (int off = 16; off; off >>= 1)
        cntAbove += __shfl_down_sync(0xffffffffu, cntAbove, off);
    if (lane == 0) sred[threadIdx.x >> 5] = cntAbove;
    __syncthreads();
    if (threadIdx.x == 0)
        g_babove[blk] = sred[0] + sred[1] + sred[2] + sred[3];
    for (int i = threadIdx.x; i < NW1; i += 128)
        g_bhist[blk][i] = wh[i];
}

// ---------------- warp inclusive suffix sum (lane..31) ----------------
__device__ __forceinline__ unsigned int warp_suffix(unsigned int v, int lane) {
    #pragma unroll
    for (int off = 1; off < 32; off <<= 1) {
        unsigned int u = __shfl_down_sync(0xffffffffu, v, off);
        if (lane + off < 32) v += u;
    }
    return v;
}

// ---------------- K2: sum block hists, locate level-1 bins (2-barrier scan) -------------
__global__ __launch_bounds__(1024) void coarse_select_win() {
    __shared__ unsigned int ws[32];
    __shared__ unsigned int sw[32];
    __shared__ unsigned int sga;
    const int p = blockIdx.x, t = threadIdx.x;
    const int lane = t & 31, wid = t >> 5;
    const int pr = p >> 3, pc = p & 7;

    // zero the sub-hist for this patch (runs before refine_pass)
    g_sub[p][0][t] = 0u;
    g_sub[p][1][t] = 0u;

    // sum the per-block hists (bins >= NW1 are zero)
    unsigned int c = 0;
    if (t < NW1) {
        #pragma unroll 4
        for (int s = 0; s < BPPY; s++)
            c += g_bhist[(pr * BPPY + s) * 8 + pc][t];
    }
    unsigned int s = warp_suffix(c, lane);
    if (lane == 0) ws[wid] = s;

    if (wid == 1) {  // warp 1 also sums the per-block above-counts (BPPY = 32)
        unsigned int a = g_babove[(pr * BPPY + lane) * 8 + pc];
        #pragma unroll
        for (int off = 16; off; off >>= 1)
            a += __shfl_down_sync(0xffffffffu, a, off);
        if (lane == 0) sga = a;
    }
    __syncthreads();
    if (wid == 0) sw[lane] = warp_suffix(ws[lane], lane);
    __syncthreads();

    const unsigned int ga = sga;
    const unsigned int total_in = sw[0];
    unsigned int above = (s - c) + ((wid < 31) ? sw[wid + 1] : 0u) + ga;

    if (t == 0)
        g_need[p] = (ga >= K2) || (ga + total_in < K1) ? 1 : 0;

    if (above < K1 && K1 <= above + c) { g_sel[p][0] = (unsigned)t; g_sel[p][1] = above; }
    if (above < K2 && K2 <= above + c) { g_sel[p][2] = (unsigned)t; g_sel[p][3] = above; }
}

// ---------------- K3a: sub-histogram, full re-read of g_blur (4x float4, grid 4096) --------
__global__ __launch_bounds__(256) void refine_pass() {
    __shared__ unsigned int sbin[NPATCH][2];
    if (threadIdx.x < NPATCH) {
        sbin[threadIdx.x][0] = g_sel[threadIdx.x][0];
        sbin[threadIdx.x][1] = g_sel[threadIdx.x][2];
    }
    __syncthreads();
    const float4* b4 = (const float4*)g_blur;
    const unsigned int stride = gridDim.x * 256;   // 1048576; NPIX/4 = 4*stride exactly
    const unsigned int base = blockIdx.x * 256 + threadIdx.x;
    float4 v0 = __ldg(&b4[base]);
    float4 v1 = __ldg(&b4[base + stride]);
    float4 v2 = __ldg(&b4[base + 2 * stride]);
    float4 v3 = __ldg(&b4[base + 3 * stride]);
    #pragma unroll
    for (int h = 0; h < 4; h++) {
        unsigned int ii = base + h * stride;
        const float4& vv = h == 0 ? v0 : h == 1 ? v1 : h == 2 ? v2 : v3;
        const float* vp = (const float*)&vv;
        int y = ii >> 10;
        int p = ((y >> 9) << 3) + ((ii & 1023u) >> 7);
        #pragma unroll
        for (int u = 0; u < 4; u++) {
            unsigned int wk = __float_as_uint(vp[u]) - WLO;
            if (wk < WSPAN) {
                unsigned int bin = wk >> W1SHIFT;
                if (bin == sbin[p][0]) atomicAdd(&g_sub[p][0][wk & 1023u], 1u);
                if (bin == sbin[p][1]) atomicAdd(&g_sub[p][1][wk & 1023u], 1u);
            }
        }
    }
}

// ---------------- walk (bit-faithful; lean 32-FADD batches, binary-search select) -------
// Reference: while (A <= th) th -= 0.0005f; stop at first t with A > t.
// Invariant at batch entry: A <= th. Monotone decreasing t_i => stop is in this
// batch iff A > t32; exact index by 5-level binary search (off the hot path).
// Identical float sequence + strict-compare stop condition.
__device__ __forceinline__ float walk_down(float th, float A) {
    if (!(A <= th)) return th;
    for (int g = 0; g < 700; g++) {
        float t1  = th  - 0.0005f;  float t2  = t1  - 0.0005f;
        float t3  = t2  - 0.0005f;  float t4  = t3  - 0.0005f;
        float t5  = t4  - 0.0005f;  float t6  = t5  - 0.0005f;
        float t7  = t6  - 0.0005f;  float t8  = t7  - 0.0005f;
        float t9  = t8  - 0.0005f;  float t10 = t9  - 0.0005f;
        float t11 = t10 - 0.0005f;  float t12 = t11 - 0.0005f;
        float t13 = t12 - 0.0005f;  float t14 = t13 - 0.0005f;
        float t15 = t14 - 0.0005f;  float t16 = t15 - 0.0005f;
        float t17 = t16 - 0.0005f;  float t18 = t17 - 0.0005f;
        float t19 = t18 - 0.0005f;  float t20 = t19 - 0.0005f;
        float t21 = t20 - 0.0005f;  float t22 = t21 - 0.0005f;
        float t23 = t22 - 0.0005f;  float t24 = t23 - 0.0005f;
        float t25 = t24 - 0.0005f;  float t26 = t25 - 0.0005f;
        float t27 = t26 - 0.0005f;  float t28 = t27 - 0.0005f;
        float t29 = t28 - 0.0005f;  float t30 = t29 - 0.0005f;
        float t31 = t30 - 0.0005f;  float t32 = t31 - 0.0005f;
        if (A > t32) {   // stop is inside this batch: 5-level binary search (monotone)
            float r;
            if (A > t16) {
                if (A > t8)
                    r = (A > t4) ? ((A > t2) ? ((A > t1) ? t1 : t2) : ((A > t3) ? t3 : t4))
                                 : ((A > t6) ? ((A > t5) ? t5 : t6) : ((A > t7) ? t7 : t8));
                else
                    r = (A > t12) ? ((A > t10) ? ((A > t9)  ? t9  : t10) : ((A > t11) ? t11 : t12))
                                  : ((A > t14) ? ((A > t13) ? t13 : t14) : ((A > t15) ? t15 : t16));
            } else {
                if (A > t24)
                    r = (A > t20) ? ((A > t18) ? ((A > t17) ? t17 : t18) : ((A > t19) ? t19 : t20))
                                  : ((A > t22) ? ((A > t21) ? t21 : t22) : ((A > t23) ? t23 : t24));
                else
                    r = (A > t28) ? ((A > t26) ? ((A > t25) ? t25 : t26) : ((A > t27) ? t27 : t28))
                                  : ((A > t30) ? ((A > t29) ? t29 : t30) : ((A > t31) ? t31 : t32));
            }
            return r;
        }
        th = t32;
    }
    return th;
}
// Reference: while (B > th) th += 0.0005f; stop at first t with B <= t.
__device__ __forceinline__ float walk_up(float th, float B) {
    if (!(B > th)) return th;
    for (int g = 0; g < 700; g++) {
        float t1  = th  + 0.0005f;  float t2  = t1  + 0.0005f;
        float t3  = t2  + 0.0005f;  float t4  = t3  + 0.0005f;
        float t5  = t4  + 0.0005f;  float t6  = t5  + 0.0005f;
        float t7  = t6  + 0.0005f;  float t8  = t7  + 0.0005f;
        float t9  = t8  + 0.0005f;  float t10 = t9  + 0.0005f;
        float t11 = t10 + 0.0005f;  float t12 = t11 + 0.0005f;
        float t13 = t12 + 0.0005f;  float t14 = t13 + 0.0005f;
        float t15 = t14 + 0.0005f;  float t16 = t15 + 0.0005f;
        float t17 = t16 + 0.0005f;  float t18 = t17 + 0.0005f;
        float t19 = t18 + 0.0005f;  float t20 = t19 + 0.0005f;
        float t21 = t20 + 0.0005f;  float t22 = t21 + 0.0005f;
        float t23 = t22 + 0.0005f;  float t24 = t23 + 0.0005f;
        float t25 = t24 + 0.0005f;  float t26 = t25 + 0.0005f;
        float t27 = t26 + 0.0005f;  float t28 = t27 + 0.0005f;
        float t29 = t28 + 0.0005f;  float t30 = t29 + 0.0005f;
        float t31 = t30 + 0.0005f;  float t32 = t31 + 0.0005f;
        if (B <= t32) {  // stop inside batch: monotone increasing, 5-level search
            float r;
            if (B <= t16) {
                if (B <= t8)
                    r = (B <= t4) ? ((B <= t2) ? ((B <= t1) ? t1 : t2) : ((B <= t3) ? t3 : t4))
                                  : ((B <= t6) ? ((B <= t5) ? t5 : t6) : ((B <= t7) ? t7 : t8));
                else
                    r = (B <= t12) ? ((B <= t10) ? ((B <= t9)  ? t9  : t10) : ((B <= t11) ? t11 : t12))
                                   : ((B <= t14) ? ((B <= t13) ? t13 : t14) : ((B <= t15) ? t15 : t16));
            } else {
                if (B <= t24)
                    r = (B <= t20) ? ((B <= t18) ? ((B <= t17) ? t17 : t18) : ((B <= t19) ? t19 : t20))
                                   : ((B <= t22) ? ((B <= t21) ? t21 : t22) : ((B <= t23) ? t23 : t24));
                else
                    r = (B <= t28) ? ((B <= t26) ? ((B <= t25) ? t25 : t26) : ((B <= t27) ? t27 : t28))
                                   : ((B <= t30) ? ((B <= t29) ? t29 : t30) : ((B <= t31) ? t31 : t32));
            }
            return r;
        }
        th = t32;
    }
    return th;
}

// ---------------- K3b: exact key within level-1 bin (+ fallback) + fused walk -------------
__global__ __launch_bounds__(1024) void refine_select_fb() {
    __shared__ unsigned int ws[32];
    __shared__ unsigned int sw[32];
    __shared__ unsigned int scnt;
    __shared__ int slast;
    __shared__ unsigned int skey[NPATCH][2];
    const int p = blockIdx.x, t = threadIdx.x;
    const int lane = t & 31, wid = t >> 5;

    if (!g_need[p]) {
        for (int q = 0; q < 2; q++) {
            const unsigned int bin = g_sel[p][q * 2];
            const unsigned int ab  = g_sel[p][q * 2 + 1];
            const unsigned int r   = (q ? K2 : K1) - ab;

            unsigned int c = g_sub[p][q][t];
            unsigned int s = warp_suffix(c, lane);
            if (lane == 0) ws[wid] = s;
            __syncthreads();
            if (wid == 0) sw[lane] = warp_suffix(ws[lane], lane);
            if (t == 0) g_key[p][q] = WLO + (bin << W1SHIFT);
            __syncthreads();
            unsigned int above = (s - c) + ((wid < 31) ? sw[wid + 1] : 0u);
            if (above < r && r <= above + c)
                g_key[p][q] = WLO + (bin << W1SHIFT) + (unsigned)t;
            __syncthreads();
        }
    } else {
        // exact fallback: binary search on the key over the whole patch
        const float* base = g_blur + ((p >> 3) * 512) * HW + (p & 7) * 512;
        for (int q = 0; q < 2; q++) {
            const unsigned int K = q ? K2 : K1;
            unsigned int lo = 0u, hi = 0x40000000u;
            while (hi - lo > 1u) {
                unsigned int mid = lo + ((hi - lo) >> 1);
                unsigned int cnt = 0;
                for (int i = t; i < 512 * 512; i += 1024) {
                    unsigned int key = __float_as_uint(base[(i >> 9) * HW + (i & 511)]);
                    cnt += (key >= mid) ? 1u : 0u;
                }
                #pragma unroll
                for (int off = 16; off; off >>= 1)
                    cnt += __shfl_down_sync(0xffffffffu, cnt, off);
                if (lane == 0) ws[wid] = cnt;
                __syncthreads();
                if (t == 0) {
                    unsigned int s = 0;
                    for (int i = 0; i < 32; i++) s += ws[i];
                    scnt = s;
                }
                __syncthreads();
                if (scnt >= K) lo = mid; else hi = mid;
                __syncthreads();
            }
            if (t == 0) g_key[p][q] = lo;
            __syncthreads();
        }
    }

    // ---- fused walk: last block runs the serial threshold walk ----
    __syncthreads();
    __threadfence();
    if (t == 0)
        slast = (atomicAdd(&g_done, 1u) == NPATCH - 1) ? 1 : 0;
    __syncthreads();
    if (slast) {
        if (t < NPATCH) {   // parallel key preload (MLP across 64 threads)
            skey[t][0] = *((volatile unsigned int*)&g_key[t][0]);
            skey[t][1] = *((volatile unsigned int*)&g_key[t][1]);
        }
        __syncthreads();
        if (t == 0) {
            float th = 0.5f;
            for (int pp = 0; pp < NPATCH; pp++) {
                float A = __uint_as_float(skey[pp][0]);
                float B = __uint_as_float(skey[pp][1]);
                th = walk_down(th, A);
                th = walk_up(th, B);
                g_th[pp] = th;
            }
            __threadfence();
            g_done = 0;   // reset for graph replay determinism
        }
    }
}

// ---------------- K5: bit-packed binarize + close (dilate5, erode5) ----------------
#define CTW  256
#define CTH  128
#define WPR  10
#define TROWS 136
__global__ __launch_bounds__(256) void close_k(float* __restrict__ out) {
    __shared__ unsigned int A[TROWS][WPR];
    __shared__ unsigned int B[TROWS][WPR];
    __shared__ float sth[NPATCH];
    const int t = threadIdx.x;
    if (t < NPATCH) sth[t] = g_th[t];
    __syncthreads();

    const int gx0 = blockIdx.x * CTW;
    const int gy0 = blockIdx.y * CTH;
    const int lane = t & 31, wid = t >> 5;
    const bool xsafe = (gx0 >= 32) && (gx0 + CTW + 32 <= HW);

    // binarize -> packed words
    for (int rr = 0; rr < TROWS / 8; rr++) {       // 17 rows per warp
        const int r  = wid + rr * 8;
        const int gy = gy0 + r - 4;
        const bool gyok = (unsigned)gy < HW;
        if (xsafe && gyok) {
            const float4* rowp = (const float4*)(g_blur + (size_t)gy * HW + (gx0 - 32));
            const int prow = (gy >> 9) << 3;
            #pragma unroll
            for (int ch = 0; ch < 2; ch++) {
                float4 a = rowp[ch * 32 + lane];
                int gx = gx0 - 32 + ch * 128 + lane * 4;
                float th = sth[prow + (gx >> 9)];
                unsigned int nib = (unsigned)(a.x > th) | ((unsigned)(a.y > th) << 1)
                                 | ((unsigned)(a.z > th) << 2) | ((unsigned)(a.w > th) << 3);
                unsigned int comb = nib << ((lane & 7) * 4);
                comb |= __shfl_xor_sync(0xffffffffu, comb, 1);
                comb |= __shfl_xor_sync(0xffffffffu, comb, 2);
                comb |= __shfl_xor_sync(0xffffffffu, comb, 4);
                if ((lane & 7) == 0) A[r][ch * 4 + (lane >> 3)] = comb;
            }
            if (lane < 16) {
                float4 a = rowp[64 + lane];
                int gx = gx0 - 32 + 256 + lane * 4;
                float th = sth[prow + (gx >> 9)];
                unsigned int nib = (unsigned)(a.x > th) | ((unsigned)(a.y > th) << 1)
                                 | ((unsigned)(a.z > th) << 2) | ((unsigned)(a.w > th) << 3);
                unsigned int comb = nib << ((lane & 7) * 4);
                comb |= __shfl_xor_sync(0x0000ffffu, comb, 1);
                comb |= __shfl_xor_sync(0x0000ffffu, comb, 2);
                comb |= __shfl_xor_sync(0x0000ffffu, comb, 4);
                if ((lane & 7) == 0) A[r][8 + (lane >> 3)] = comb;
            }
        } else if (!gyok) {
            if (lane < WPR) A[r][lane] = 0u;
        } else {
            float v[WPR];
            #pragma unroll
            for (int wc = 0; wc < WPR; wc++) {
                int gx = gx0 + (wc - 1) * 32 + lane;
                v[wc] = ((unsigned)gx < HW) ? g_blur[(size_t)gy * HW + gx] : 0.0f;
            }
            #pragma unroll
            for (int wc = 0; wc < WPR; wc++) {
                int gx = gx0 + (wc - 1) * 32 + lane;
                unsigned int bit = 0;
                if ((unsigned)gx < HW)
                    bit = (v[wc] > sth[((gy >> 9) << 3) + (gx >> 9)]) ? 1u : 0u;
                unsigned int word = __ballot_sync(0xffffffffu, bit);
                if (lane == 0) A[r][wc] = word;
            }
        }
    }
    __syncthreads();

    for (int i = t; i < TROWS * WPR; i += 256) {
        int r = i / WPR, wc = i % WPR;
        unsigned int wv = A[r][wc];
        unsigned int lw = wc > 0       ? A[r][wc - 1] : 0u;
        unsigned int rw = wc < WPR - 1 ? A[r][wc + 1] : 0u;
        B[r][wc] = wv | __funnelshift_r(wv, rw, 1) | __funnelshift_r(wv, rw, 2)
                      | __funnelshift_l(lw, wv, 1) | __funnelshift_l(lw, wv, 2);
    }
    __syncthreads();

    for (int i = t; i < TROWS * WPR; i += 256) {
        int r = i / WPR, wc = i % WPR;
        unsigned int d = 0u;
        if (r >= 2 && r < TROWS - 2)
            d = B[r-2][wc] | B[r-1][wc] | B[r][wc] | B[r+1][wc] | B[r+2][wc];
        int gy = gy0 + r - 4;
        bool xout = (wc == 0 && gx0 == 0) || (wc == WPR - 1 && gx0 + CTW == HW);
        if ((unsigned)gy >= HW || xout) d = 0xffffffffu;
        A[r][wc] = d;
    }
    __syncthreads();

    for (int i = t; i < TROWS * WPR; i += 256) {
        int r = i / WPR, wc = i % WPR;
        unsigned int wv = A[r][wc];
        unsigned int lw = wc > 0       ? A[r][wc - 1] : 0xffffffffu;
        unsigned int rw = wc < WPR - 1 ? A[r][wc + 1] : 0xffffffffu;
        B[r][wc] = wv & __funnelshift_r(wv, rw, 1) & __funnelshift_r(wv, rw, 2)
                      & __funnelshift_l(lw, wv, 1) & __funnelshift_l(lw, wv, 2);
    }
    __syncthreads();

    for (int i = t; i < CTH * 8; i += 256) {
        int r = (i >> 3) + 4, wc = (i & 7) + 1;
        unsigned int v = B[r-2][wc] & B[r-1][wc] & B[r][wc] & B[r+1][wc] & B[r+2][wc];
        int gy = gy0 + r - 4;
        int gx = gx0 + (wc - 1) * 32;
        float4* o = (float4*)&out[(size_t)gy * HW + gx];
        #pragma unroll
        for (int q = 0; q < 8; q++) {
            float4 fv;
            fv.x = (v >> (q * 4 + 0)) & 1u ? 1.0f : 0.0f;
            fv.y = (v >> (q * 4 + 1)) & 1u ? 1.0f : 0.0f;
            fv.z = (v >> (q * 4 + 2)) & 1u ? 1.0f : 0.0f;
            fv.w = (v >> (q * 4 + 3)) & 1u ? 1.0f : 0.0f;
            o[q] = fv;
        }
    }
}

// ---------------- launch ----------------
extern "C" void kernel_launch(void* const* d_in, const int* in_sizes, int n_in,
                              void* d_out, int out_size) {
    const float* x  = (const float*)d_in[0];
    const float* bk = (const float*)d_in[1];
    float* out = (float*)d_out;
    (void)in_sizes; (void)n_in; (void)out_size;

    blur_hist<<<dim3(HW / 512, HW / RPB), 128>>>(x, bk);
    coarse_select_win<<<NPATCH, 1024>>>();
    refine_pass<<<4096, 256>>>();
    refine_select_fb<<<NPATCH, 1024>>>();   // walk fused (32-step batches)
    close_k<<<dim3(HW / CTW, HW / CTH), 256>>>(out);
}

// round 17
// speedup vs baseline: 1.3761x; 1.0739x over previous
#include <cuda_runtime.h>

// ---------------- problem constants ----------------
#define HW      4096
#define NPIX    (HW*HW)
#define NPATCH  64
#define K1      31458u   // loop1 continues iff count(v>th) <= 31457  <=>  v_(31458) <= th
#define K2      20972u   // loop2 continues iff count(v>th) >= 20972  <=>  v_(20972) >  th

// value window (verified per-patch; exact fallback if violated)
#define WLO     0x3F0E0000u   // ~0.5547
#define WHI     0x3F1A0000u   // ~0.6016
#define WSPAN   0xC0000u
#define NW1     768           // level-1 bins of 1024 keys each
#define W1SHIFT 10

// 0.0005f = 8388.6083984375 ulp in binade [0.5,1): every RN(t -/+ 0.0005f) step
// moves the bit pattern by exactly -/+8389 (frac .6084 always rounds outward; no ties).
#define STEP_ULP 8389u
#define BIN_LO   0x3F000000u   // 0.5f
#define BIN_HI   0x3F7FFFFFu   // just under 1.0f

#define RPB     16            // rows per blur block
#define BPPY    (512 / RPB)   // blur blocks per patch, vertically (32)
#define NBLK    (8 * (HW / RPB))   // total blur blocks (2048)

// ---------------- device scratch ----------------
__device__ float        g_blur[NPIX];
__device__ unsigned int g_bhist[NBLK][NW1];      // per-block hist (plain stores, no zeroing)
__device__ unsigned int g_babove[NBLK];
__device__ int          g_need [NPATCH];         // exact-fallback flag (plain store)
__device__ unsigned int g_sub  [NPATCH][2][1024];
__device__ unsigned int g_sel  [NPATCH][4];      // bin1, above1, bin2, above2
__device__ unsigned int g_key  [NPATCH][2];
__device__ float        g_th   [NPATCH];
__device__ unsigned int g_done = 0;              // last-block counter (reset after use)

// ---------------- K1: blur (circular register window, fully unrolled) + per-block hist ----
// Per-pixel 25-tap fmaf chain IDENTICAL to the passing version (kw outer, kh inner).
__device__ __forceinline__ void load_row(float* dst, const float* __restrict__ x,
                                         int yy, int c0, bool safe) {
    if (yy < 0 || yy >= HW) {
        #pragma unroll
        for (int j = 0; j < 12; j++) dst[j] = 0.0f;
    } else if (safe) {
        const float4* p = (const float4*)&x[yy * HW + c0 - 4];
        float4 a = __ldg(p), b = __ldg(p + 1), c = __ldg(p + 2);
        dst[0]=a.x; dst[1]=a.y; dst[2]=a.z;  dst[3]=a.w;
        dst[4]=b.x; dst[5]=b.y; dst[6]=b.z;  dst[7]=b.w;
        dst[8]=c.x; dst[9]=c.y; dst[10]=c.z; dst[11]=c.w;
    } else {
        #pragma unroll
        for (int j = 0; j < 12; j++) {
            int cc = c0 - 4 + j;
            dst[j] = (cc >= 0 && cc < HW) ? __ldg(&x[yy * HW + cc]) : 0.0f;
        }
    }
}

__global__ __launch_bounds__(128) void blur_hist(const float* __restrict__ x,
                                                 const float* __restrict__ bk) {
    __shared__ unsigned int wh[NW1];
    __shared__ unsigned int sred[4];
    for (int i = threadIdx.x; i < NW1; i += 128) wh[i] = 0u;
    __syncthreads();

    const float w  = bk[0];
    const int   c0 = blockIdx.x * 512 + threadIdx.x * 4;
    const int   y0 = blockIdx.y * RPB;
    const int   blk = blockIdx.y * 8 + blockIdx.x;
    const bool  safe = (c0 >= 4) && (c0 <= HW - 9);
    const int   lane = threadIdx.x & 31;
    unsigned int cntAbove = 0;

    float f[5][12];
    #pragma unroll
    for (int i = 0; i < 4; i++) load_row(f[i], x, y0 - 2 + i, c0, safe);

    #pragma unroll
    for (int k = 0; k < RPB; k++) {
        const int y = y0 + k;
        load_row(f[(k + 4) % 5], x, y + 2, c0, safe);

        float4 o;
        float* op = (float*)&o;
        #pragma unroll
        for (int u = 0; u < 4; u++) {
            float acc = 0.0f;
            #pragma unroll
            for (int j = 0; j < 5; j++)        // kw outer
                #pragma unroll
                for (int i = 0; i < 5; i++)    // kh inner (fastest) — Eigen order
                    acc = fmaf(f[(k + i) % 5][u + j + 2], w, acc);
            op[u] = acc;
            unsigned int key = __float_as_uint(acc);
            cntAbove += (key >= WHI) ? 1u : 0u;
            if (key - WLO < WSPAN)
                atomicAdd(&wh[(key - WLO) >> W1SHIFT], 1u);
        }
        *(float4*)&g_blur[y * HW + c0] = o;
    }

    #pragma unroll
    for (int off = 16; off; off >>= 1)
        cntAbove += __shfl_down_sync(0xffffffffu, cntAbove, off);
    if (lane == 0) sred[threadIdx.x >> 5] = cntAbove;
    __syncthreads();
    if (threadIdx.x == 0)
        g_babove[blk] = sred[0] + sred[1] + sred[2] + sred[3];
    for (int i = threadIdx.x; i < NW1; i += 128)
        g_bhist[blk][i] = wh[i];
}

// ---------------- warp inclusive suffix sum (lane..31) ----------------
__device__ __forceinline__ unsigned int warp_suffix(unsigned int v, int lane) {
    #pragma unroll
    for (int off = 1; off < 32; off <<= 1) {
        unsigned int u = __shfl_down_sync(0xffffffffu, v, off);
        if (lane + off < 32) v += u;
    }
    return v;
}

// ---------------- K2: sum block hists, locate level-1 bins (2-barrier scan) -------------
__global__ __launch_bounds__(1024) void coarse_select_win() {
    __shared__ unsigned int ws[32];
    __shared__ unsigned int sw[32];
    __shared__ unsigned int sga;
    const int p = blockIdx.x, t = threadIdx.x;
    const int lane = t & 31, wid = t >> 5;
    const int pr = p >> 3, pc = p & 7;

    // zero the sub-hist for this patch (runs before refine_pass)
    g_sub[p][0][t] = 0u;
    g_sub[p][1][t] = 0u;

    // sum the per-block hists (bins >= NW1 are zero)
    unsigned int c = 0;
    if (t < NW1) {
        #pragma unroll 4
        for (int s = 0; s < BPPY; s++)
            c += g_bhist[(pr * BPPY + s) * 8 + pc][t];
    }
    unsigned int s = warp_suffix(c, lane);
    if (lane == 0) ws[wid] = s;

    if (wid == 1) {  // warp 1 also sums the per-block above-counts (BPPY = 32)
        unsigned int a = g_babove[(pr * BPPY + lane) * 8 + pc];
        #pragma unroll
        for (int off = 16; off; off >>= 1)
            a += __shfl_down_sync(0xffffffffu, a, off);
        if (lane == 0) sga = a;
    }
    __syncthreads();
    if (wid == 0) sw[lane] = warp_suffix(ws[lane], lane);
    __syncthreads();

    const unsigned int ga = sga;
    const unsigned int total_in = sw[0];
    unsigned int above = (s - c) + ((wid < 31) ? sw[wid + 1] : 0u) + ga;

    if (t == 0)
        g_need[p] = (ga >= K2) || (ga + total_in < K1) ? 1 : 0;

    if (above < K1 && K1 <= above + c) { g_sel[p][0] = (unsigned)t; g_sel[p][1] = above; }
    if (above < K2 && K2 <= above + c) { g_sel[p][2] = (unsigned)t; g_sel[p][3] = above; }
}

// ---------------- K3a: sub-histogram, full re-read of g_blur (4x float4, grid 4096) --------
__global__ __launch_bounds__(256) void refine_pass() {
    __shared__ unsigned int sbin[NPATCH][2];
    if (threadIdx.x < NPATCH) {
        sbin[threadIdx.x][0] = g_sel[threadIdx.x][0];
        sbin[threadIdx.x][1] = g_sel[threadIdx.x][2];
    }
    __syncthreads();
    const float4* b4 = (const float4*)g_blur;
    const unsigned int stride = gridDim.x * 256;   // 1048576; NPIX/4 = 4*stride exactly
    const unsigned int base = blockIdx.x * 256 + threadIdx.x;
    float4 v0 = __ldg(&b4[base]);
    float4 v1 = __ldg(&b4[base + stride]);
    float4 v2 = __ldg(&b4[base + 2 * stride]);
    float4 v3 = __ldg(&b4[base + 3 * stride]);
    #pragma unroll
    for (int h = 0; h < 4; h++) {
        unsigned int ii = base + h * stride;
        const float4& vv = h == 0 ? v0 : h == 1 ? v1 : h == 2 ? v2 : v3;
        const float* vp = (const float*)&vv;
        int y = ii >> 10;
        int p = ((y >> 9) << 3) + ((ii & 1023u) >> 7);
        #pragma unroll
        for (int u = 0; u < 4; u++) {
            unsigned int wk = __float_as_uint(vp[u]) - WLO;
            if (wk < WSPAN) {
                unsigned int bin = wk >> W1SHIFT;
                if (bin == sbin[p][0]) atomicAdd(&g_sub[p][0][wk & 1023u], 1u);
                if (bin == sbin[p][1]) atomicAdd(&g_sub[p][1][wk & 1023u], 1u);
            }
        }
    }
}

// ---------------- walk: exact closed form on float bit patterns ----------------
// Within binade [0.5,1), every "th -= 0.0005f" is exactly -STEP_ULP on the bits and
// every "th += 0.0005f" is exactly +STEP_ULP (0.0005f = 8388.6084 ulp; frac .6084
// always rounds outward, never a tie). Positive-float compares == bit compares.
// Iterative exact fallback covers any out-of-binade case (never hit in practice).
__device__ __forceinline__ unsigned int walk_down_bits(unsigned int th, unsigned int A) {
    if (A > th) return th;                       // while-condition false at entry
    if (th >= BIN_LO && th <= BIN_HI && A >= BIN_LO && A <= BIN_HI) {
        unsigned int i   = (th - A) / STEP_ULP + 1u;   // first i with th - i*step < A
        unsigned int res = th - i * STEP_ULP;
        if (res >= BIN_LO) return res;
    }
    float t = __uint_as_float(th), Af = __uint_as_float(A);
    int g = 0;
    while (Af <= t && g < 200000) { t -= 0.0005f; g++; }
    return __float_as_uint(t);
}
__device__ __forceinline__ unsigned int walk_up_bits(unsigned int th, unsigned int B) {
    if (B <= th) return th;                      // while-condition false at entry
    if (th >= BIN_LO && th <= BIN_HI && B >= BIN_LO && B <= BIN_HI) {
        unsigned int i   = (B - th + STEP_ULP - 1u) / STEP_ULP;  // first i with th+i*step >= B
        unsigned int res = th + i * STEP_ULP;
        if (res <= BIN_HI) return res;
    }
    float t = __uint_as_float(th), Bf = __uint_as_float(B);
    int g = 0;
    while (Bf > t && g < 200000) { t += 0.0005f; g++; }
    return __float_as_uint(t);
}

// ---------------- K3b: exact key within level-1 bin (+ fallback) + fused walk -------------
__global__ __launch_bounds__(1024) void refine_select_fb() {
    __shared__ unsigned int ws[32];
    __shared__ unsigned int sw[32];
    __shared__ unsigned int scnt;
    __shared__ int slast;
    __shared__ unsigned int skey[NPATCH][2];
    const int p = blockIdx.x, t = threadIdx.x;
    const int lane = t & 31, wid = t >> 5;

    if (!g_need[p]) {
        for (int q = 0; q < 2; q++) {
            const unsigned int bin = g_sel[p][q * 2];
            const unsigned int ab  = g_sel[p][q * 2 + 1];
            const unsigned int r   = (q ? K2 : K1) - ab;

            unsigned int c = g_sub[p][q][t];
            unsigned int s = warp_suffix(c, lane);
            if (lane == 0) ws[wid] = s;
            __syncthreads();
            if (wid == 0) sw[lane] = warp_suffix(ws[lane], lane);
            if (t == 0) g_key[p][q] = WLO + (bin << W1SHIFT);
            __syncthreads();
            unsigned int above = (s - c) + ((wid < 31) ? sw[wid + 1] : 0u);
            if (above < r && r <= above + c)
                g_key[p][q] = WLO + (bin << W1SHIFT) + (unsigned)t;
            __syncthreads();
        }
    } else {
        // exact fallback: binary search on the key over the whole patch
        const float* base = g_blur + ((p >> 3) * 512) * HW + (p & 7) * 512;
        for (int q = 0; q < 2; q++) {
            const unsigned int K = q ? K2 : K1;
            unsigned int lo = 0u, hi = 0x40000000u;
            while (hi - lo > 1u) {
                unsigned int mid = lo + ((hi - lo) >> 1);
                unsigned int cnt = 0;
                for (int i = t; i < 512 * 512; i += 1024) {
                    unsigned int key = __float_as_uint(base[(i >> 9) * HW + (i & 511)]);
                    cnt += (key >= mid) ? 1u : 0u;
                }
                #pragma unroll
                for (int off = 16; off; off >>= 1)
                    cnt += __shfl_down_sync(0xffffffffu, cnt, off);
                if (lane == 0) ws[wid] = cnt;
                __syncthreads();
                if (t == 0) {
                    unsigned int s = 0;
                    for (int i = 0; i < 32; i++) s += ws[i];
                    scnt = s;
                }
                __syncthreads();
                if (scnt >= K) lo = mid; else hi = mid;
                __syncthreads();
            }
            if (t == 0) g_key[p][q] = lo;
            __syncthreads();
        }
    }

    // ---- fused walk: last block runs the (now closed-form) threshold walk ----
    __syncthreads();
    __threadfence();
    if (t == 0)
        slast = (atomicAdd(&g_done, 1u) == NPATCH - 1) ? 1 : 0;
    __syncthreads();
    if (slast) {
        if (t < NPATCH) {   // parallel key preload
            skey[t][0] = *((volatile unsigned int*)&g_key[t][0]);
            skey[t][1] = *((volatile unsigned int*)&g_key[t][1]);
        }
        __syncthreads();
        if (t == 0) {
            unsigned int th = BIN_LO;   // 0.5f
            for (int pp = 0; pp < NPATCH; pp++) {
                th = walk_down_bits(th, skey[pp][0]);
                th = walk_up_bits(th, skey[pp][1]);
                g_th[pp] = __uint_as_float(th);
            }
            __threadfence();
            g_done = 0;   // reset for graph replay determinism
        }
    }
}

// ---------------- K5: bit-packed binarize + close (dilate5, erode5) ----------------
#define CTW  256
#define CTH  128
#define WPR  10
#define TROWS 136
__global__ __launch_bounds__(256) void close_k(float* __restrict__ out) {
    __shared__ unsigned int A[TROWS][WPR];
    __shared__ unsigned int B[TROWS][WPR];
    __shared__ float sth[NPATCH];
    const int t = threadIdx.x;
    if (t < NPATCH) sth[t] = g_th[t];
    __syncthreads();

    const int gx0 = blockIdx.x * CTW;
    const int gy0 = blockIdx.y * CTH;
    const int lane = t & 31, wid = t >> 5;
    const bool xsafe = (gx0 >= 32) && (gx0 + CTW + 32 <= HW);

    // binarize -> packed words
    for (int rr = 0; rr < TROWS / 8; rr++) {       // 17 rows per warp
        const int r  = wid + rr * 8;
        const int gy = gy0 + r - 4;
        const bool gyok = (unsigned)gy < HW;
        if (xsafe && gyok) {
            const float4* rowp = (const float4*)(g_blur + (size_t)gy * HW + (gx0 - 32));
            const int prow = (gy >> 9) << 3;
            #pragma unroll
            for (int ch = 0; ch < 2; ch++) {
                float4 a = rowp[ch * 32 + lane];
                int gx = gx0 - 32 + ch * 128 + lane * 4;
                float th = sth[prow + (gx >> 9)];
                unsigned int nib = (unsigned)(a.x > th) | ((unsigned)(a.y > th) << 1)
                                 | ((unsigned)(a.z > th) << 2) | ((unsigned)(a.w > th) << 3);
                unsigned int comb = nib << ((lane & 7) * 4);
                comb |= __shfl_xor_sync(0xffffffffu, comb, 1);
                comb |= __shfl_xor_sync(0xffffffffu, comb, 2);
                comb |= __shfl_xor_sync(0xffffffffu, comb, 4);
                if ((lane & 7) == 0) A[r][ch * 4 + (lane >> 3)] = comb;
            }
            if (lane < 16) {
                float4 a = rowp[64 + lane];
                int gx = gx0 - 32 + 256 + lane * 4;
                float th = sth[prow + (gx >> 9)];
                unsigned int nib = (unsigned)(a.x > th) | ((unsigned)(a.y > th) << 1)
                                 | ((unsigned)(a.z > th) << 2) | ((unsigned)(a.w > th) << 3);
                unsigned int comb = nib << ((lane & 7) * 4);
                comb |= __shfl_xor_sync(0x0000ffffu, comb, 1);
                comb |= __shfl_xor_sync(0x0000ffffu, comb, 2);
                comb |= __shfl_xor_sync(0x0000ffffu, comb, 4);
                if ((lane & 7) == 0) A[r][8 + (lane >> 3)] = comb;
            }
        } else if (!gyok) {
            if (lane < WPR) A[r][lane] = 0u;
        } else {
            float v[WPR];
            #pragma unroll
            for (int wc = 0; wc < WPR; wc++) {
                int gx = gx0 + (wc - 1) * 32 + lane;
                v[wc] = ((unsigned)gx < HW) ? g_blur[(size_t)gy * HW + gx] : 0.0f;
            }
            #pragma unroll
            for (int wc = 0; wc < WPR; wc++) {
                int gx = gx0 + (wc - 1) * 32 + lane;
                unsigned int bit = 0;
                if ((unsigned)gx < HW)
                    bit = (v[wc] > sth[((gy >> 9) << 3) + (gx >> 9)]) ? 1u : 0u;
                unsigned int word = __ballot_sync(0xffffffffu, bit);
                if (lane == 0) A[r][wc] = word;
            }
        }
    }
    __syncthreads();

    for (int i = t; i < TROWS * WPR; i += 256) {
        int r = i / WPR, wc = i % WPR;
        unsigned int wv = A[r][wc];
        unsigned int lw = wc > 0       ? A[r][wc - 1] : 0u;
        unsigned int rw = wc < WPR - 1 ? A[r][wc + 1] : 0u;
        B[r][wc] = wv | __funnelshift_r(wv, rw, 1) | __funnelshift_r(wv, rw, 2)
                      | __funnelshift_l(lw, wv, 1) | __funnelshift_l(lw, wv, 2);
    }
    __syncthreads();

    for (int i = t; i < TROWS * WPR; i += 256) {
        int r = i / WPR, wc = i % WPR;
        unsigned int d = 0u;
        if (r >= 2 && r < TROWS - 2)
            d = B[r-2][wc] | B[r-1][wc] | B[r][wc] | B[r+1][wc] | B[r+2][wc];
        int gy = gy0 + r - 4;
        bool xout = (wc == 0 && gx0 == 0) || (wc == WPR - 1 && gx0 + CTW == HW);
        if ((unsigned)gy >= HW || xout) d = 0xffffffffu;
        A[r][wc] = d;
    }
    __syncthreads();

    for (int i = t; i < TROWS * WPR; i += 256) {
        int r = i / WPR, wc = i % WPR;
        unsigned int wv = A[r][wc];
        unsigned int lw = wc > 0       ? A[r][wc - 1] : 0xffffffffu;
        unsigned int rw = wc < WPR - 1 ? A[r][wc + 1] : 0xffffffffu;
        B[r][wc] = wv & __funnelshift_r(wv, rw, 1) & __funnelshift_r(wv, rw, 2)
                      & __funnelshift_l(lw, wv, 1) & __funnelshift_l(lw, wv, 2);
    }
    __syncthreads();

    for (int i = t; i < CTH * 8; i += 256) {
        int r = (i >> 3) + 4, wc = (i & 7) + 1;
        unsigned int v = B[r-2][wc] & B[r-1][wc] & B[r][wc] & B[r+1][wc] & B[r+2][wc];
        int gy = gy0 + r - 4;
        int gx = gx0 + (wc - 1) * 32;
        float4* o = (float4*)&out[(size_t)gy * HW + gx];
        #pragma unroll
        for (int q = 0; q < 8; q++) {
            float4 fv;
            fv.x = (v >> (q * 4 + 0)) & 1u ? 1.0f : 0.0f;
            fv.y = (v >> (q * 4 + 1)) & 1u ? 1.0f : 0.0f;
            fv.z = (v >> (q * 4 + 2)) & 1u ? 1.0f : 0.0f;
            fv.w = (v >> (q * 4 + 3)) & 1u ? 1.0f : 0.0f;
            o[q] = fv;
        }
    }
}

// ---------------- launch ----------------
extern "C" void kernel_launch(void* const* d_in, const int* in_sizes, int n_in,
                              void* d_out, int out_size) {
    const float* x  = (const float*)d_in[0];
    const float* bk = (const float*)d_in[1];
    float* out = (float*)d_out;
    (void)in_sizes; (void)n_in; (void)out_size;

    blur_hist<<<dim3(HW / 512, HW / RPB), 128>>>(x, bk);
    coarse_select_win<<<NPATCH, 1024>>>();
    refine_pass<<<4096, 256>>>();
    refine_select_fb<<<NPATCH, 1024>>>();   // walk fused (closed-form ulp arithmetic)
    close_k<<<dim3(HW / CTW, HW / CTH), 256>>>(out);
}